// round 12
// baseline (speedup 1.0000x reference)
#include <cuda_runtime.h>
#include <cuda_bf16.h>
#include <math.h>
#include <stdint.h>

#define B_  2
#define S_  2048
#define D_  2048
#define H_  16
#define HD_ 128
#define M_  (B_*S_)      // 4096 rows total

// ---------------- scratch (device globals; no allocation allowed) ----------------
__device__ float g_Q[(size_t)M_*D_];                 // fp32 proj out (pre-rope)
__device__ float g_K[(size_t)M_*D_];
__device__ float g_cos[S_*64];
__device__ float g_sin[S_*64];

__device__ __nv_bfloat16 g_xh[(size_t)M_*D_],  g_xl[(size_t)M_*D_];
__device__ __nv_bfloat16 g_Wqh[(size_t)D_*D_], g_Wql[(size_t)D_*D_];
__device__ __nv_bfloat16 g_Wkh[(size_t)D_*D_], g_Wkl[(size_t)D_*D_];
__device__ __nv_bfloat16 g_Wvh[(size_t)D_*D_], g_Wvl[(size_t)D_*D_];
__device__ __nv_bfloat16 g_Woh[(size_t)D_*D_], g_Wol[(size_t)D_*D_];
__device__ __nv_bfloat16 g_Qh[(size_t)M_*D_],  g_Ql[(size_t)M_*D_];
__device__ __nv_bfloat16 g_Kh[(size_t)M_*D_],  g_Kl[(size_t)M_*D_];
__device__ __nv_bfloat16 g_Vh[(size_t)M_*D_],  g_Vl[(size_t)M_*D_];
__device__ __nv_bfloat16 g_AOh[(size_t)M_*D_], g_AOl[(size_t)M_*D_];

// ---------------- helpers ---------------------------------------------------------
__device__ __forceinline__ uint32_t smem_u32(const void* p) {
    return (uint32_t)__cvta_generic_to_shared(p);
}
__device__ __forceinline__ void cpa16(uint32_t dst, const void* src) {
    asm volatile("cp.async.cg.shared.global [%0],[%1],16;" :: "r"(dst), "l"(src));
}
__device__ __forceinline__ void cpa_commit() { asm volatile("cp.async.commit_group;"); }
template<int N> __device__ __forceinline__ void cpa_wait() {
    asm volatile("cp.async.wait_group %0;" :: "n"(N));
}
__device__ __forceinline__ void ldsm4(uint32_t r[4], uint32_t addr) {
    asm volatile("ldmatrix.sync.aligned.m8n8.x4.shared.b16 {%0,%1,%2,%3},[%4];"
                 : "=r"(r[0]), "=r"(r[1]), "=r"(r[2]), "=r"(r[3]) : "r"(addr));
}
__device__ __forceinline__ void ldsm4t(uint32_t r[4], uint32_t addr) {
    asm volatile("ldmatrix.sync.aligned.m8n8.x4.trans.shared.b16 {%0,%1,%2,%3},[%4];"
                 : "=r"(r[0]), "=r"(r[1]), "=r"(r[2]), "=r"(r[3]) : "r"(addr));
}
__device__ __forceinline__ void mma_bf16(float d[4], const uint32_t a[4], const uint32_t b[2]) {
    asm volatile(
        "mma.sync.aligned.m16n8k16.row.col.f32.bf16.bf16.f32 "
        "{%0,%1,%2,%3},{%4,%5,%6,%7},{%8,%9},{%0,%1,%2,%3};"
        : "+f"(d[0]), "+f"(d[1]), "+f"(d[2]), "+f"(d[3])
        : "r"(a[0]), "r"(a[1]), "r"(a[2]), "r"(a[3]), "r"(b[0]), "r"(b[1]));
}
__device__ __forceinline__ void split2(float x0, float x1, uint32_t &h, uint32_t &l) {
    __nv_bfloat16 h0 = __float2bfloat16(x0);
    __nv_bfloat16 h1 = __float2bfloat16(x1);
    __nv_bfloat16 l0 = __float2bfloat16(x0 - __bfloat162float(h0));
    __nv_bfloat16 l1 = __float2bfloat16(x1 - __bfloat162float(h1));
    __nv_bfloat162 hp = __halves2bfloat162(h0, h1);
    __nv_bfloat162 lp = __halves2bfloat162(l0, l1);
    h = *reinterpret_cast<uint32_t*>(&hp);
    l = *reinterpret_cast<uint32_t*>(&lp);
}

// ---------------- elementwise fp32 -> (hi,lo) convert -----------------------------
__global__ __launch_bounds__(256)
void split_arr(const float4* __restrict__ src,
               uint2* __restrict__ h, uint2* __restrict__ l, int n4)
{
    int i = blockIdx.x * blockDim.x + threadIdx.x;
    if (i >= n4) return;
    float4 v = src[i];
    uint32_t h0, l0, h1, l1;
    split2(v.x, v.y, h0, l0);
    split2(v.z, v.w, h1, l1);
    h[i] = make_uint2(h0, h1);
    l[i] = make_uint2(l0, l1);
}

// ============================================================================
// BIG-TILE projection GEMM: C = A * B^T, 256x128 CTA, half-stage (k32)
// pipelined cp.async: ring = 2 stages x 2 halves, 3 halves in flight.
// 256 threads, 8 warps 4m x 2n, warp tile 64x64. smem 192KB (2 x 96KB stages).
// outSplit: 0 -> C fp32 ; 1 -> Ch/Cl bf16.
// ============================================================================
__global__ __launch_bounds__(256)
void gemm_big(const __nv_bfloat16* __restrict__ Agh, const __nv_bfloat16* __restrict__ Agl,
              const __nv_bfloat16* __restrict__ Bgh, const __nv_bfloat16* __restrict__ Bgl,
              float* __restrict__ C,
              __nv_bfloat16* __restrict__ Ch, __nv_bfloat16* __restrict__ Cl,
              int K, int lda, int ldb, int ldc, int outSplit)
{
    int rowBase = blockIdx.y * 256;
    int colBase = blockIdx.x * 128;

    extern __shared__ __align__(16) char sraw[];
    uint32_t sb = smem_u32(sraw);

    int tid = threadIdx.x, lane = tid & 31, w = tid >> 5;
    int wm = w >> 1, wn = w & 1;
    int lr = lane & 7, grp = lane >> 3;

    int agk = grp >> 1;
    uint32_t arow[4], arx[4];
    #pragma unroll
    for (int s = 0; s < 4; s++) {
        int r = wm * 64 + s * 16 + ((grp & 1) << 3) + lr;
        arow[s] = (uint32_t)r << 7;
        arx[s]  = r & 7;
    }
    int bgk = grp & 1;
    uint32_t brow[4], brx[4];
    #pragma unroll
    for (int p = 0; p < 4; p++) {
        int r = wn * 64 + p * 16 + ((grp >> 1) << 3) + lr;
        brow[p] = (uint32_t)r << 7;
        brx[p]  = r & 7;
    }

    float acc[4][8][4];
    #pragma unroll
    for (int s = 0; s < 4; s++)
        #pragma unroll
        for (int n = 0; n < 8; n++)
            #pragma unroll
            for (int j = 0; j < 4; j++) acc[s][n][j] = 0.f;

    int T2 = K >> 5;                      // half-stages (k32 each)

    // one half-stage = k32 = chunks [hf*4, hf*4+4) of the 128B-row layout.
    // A: thread owns row tid, 4 chunks. B: thread owns row tid&127, 2 chunks.
    auto issueHalf = [&](int u) {
        int stg = (u >> 1) & 1;
        int hf  = u & 1;
        uint32_t base = sb + (uint32_t)stg * 98304u;
        int k0 = (u >> 1) << 6;
        int ra = tid;
        #pragma unroll
        for (int i = 0; i < 4; i++) {
            int c = (hf << 2) + i;
            uint32_t dst = base + ((uint32_t)ra << 7) + (uint32_t)((c ^ (ra & 7)) << 4);
            cpa16(dst,           Agh + (size_t)(rowBase + ra) * lda + k0 + (c << 3));
            cpa16(dst + 32768u,  Agl + (size_t)(rowBase + ra) * lda + k0 + (c << 3));
        }
        int rb = tid & 127;
        #pragma unroll
        for (int i = 0; i < 2; i++) {
            int c = (hf << 2) + (i << 1) + (tid >> 7);
            uint32_t dst = base + 65536u + ((uint32_t)rb << 7) + (uint32_t)((c ^ (rb & 7)) << 4);
            cpa16(dst,           Bgh + (size_t)(colBase + rb) * ldb + k0 + (c << 3));
            cpa16(dst + 16384u,  Bgl + (size_t)(colBase + rb) * ldb + k0 + (c << 3));
        }
        cpa_commit();
    };

    issueHalf(0);
    if (T2 > 1) issueHalf(1);
    if (T2 > 2) issueHalf(2);

    for (int u = 0; u < T2; u++) {
        if (u < T2 - 2)      cpa_wait<2>();
        else if (u == T2 - 2) cpa_wait<1>();
        else                  cpa_wait<0>();
        __syncthreads();
        if (u + 3 < T2) issueHalf(u + 3);

        int stg = (u >> 1) & 1;
        int hf  = u & 1;
        uint32_t aH = sb + (uint32_t)stg * 98304u;
        uint32_t aL = aH + 32768u;
        uint32_t bH = aH + 65536u;
        uint32_t bL = aH + 81920u;

        #pragma unroll
        for (int st2 = 0; st2 < 2; st2++) {
            int st = (hf << 1) + st2;
            uint32_t Ah[4][4], Al[4][4], Bh[8][2], Bl[8][2];
            #pragma unroll
            for (int s = 0; s < 4; s++) {
                uint32_t off = arow[s] + ((((st << 1) + agk) ^ arx[s]) << 4);
                ldsm4(Ah[s], aH + off);
                ldsm4(Al[s], aL + off);
            }
            #pragma unroll
            for (int p = 0; p < 4; p++) {
                uint32_t off = brow[p] + ((((st << 1) + bgk) ^ brx[p]) << 4);
                uint32_t tr[4];
                ldsm4(tr, bH + off);
                Bh[2*p][0] = tr[0]; Bh[2*p][1] = tr[1];
                Bh[2*p+1][0] = tr[2]; Bh[2*p+1][1] = tr[3];
                ldsm4(tr, bL + off);
                Bl[2*p][0] = tr[0]; Bl[2*p][1] = tr[1];
                Bl[2*p+1][0] = tr[2]; Bl[2*p+1][1] = tr[3];
            }
            #pragma unroll
            for (int s = 0; s < 4; s++)
                #pragma unroll
                for (int n = 0; n < 8; n++) {
                    mma_bf16(acc[s][n], Ah[s], Bh[n]);
                    mma_bf16(acc[s][n], Ah[s], Bl[n]);
                    mma_bf16(acc[s][n], Al[s], Bh[n]);
                }
        }
    }

    __syncthreads();
    #pragma unroll
    for (int s = 0; s < 4; s++) {
        int r0 = rowBase + wm * 64 + s * 16 + (lane >> 2);
        #pragma unroll
        for (int n = 0; n < 8; n++) {
            int c0 = colBase + wn * 64 + n * 8 + ((lane & 3) << 1);
            if (!outSplit) {
                *(float2*)&C[(size_t)r0 * ldc + c0]       = make_float2(acc[s][n][0], acc[s][n][1]);
                *(float2*)&C[(size_t)(r0 + 8) * ldc + c0] = make_float2(acc[s][n][2], acc[s][n][3]);
            } else {
                uint32_t h0, l0, h1, l1;
                split2(acc[s][n][0], acc[s][n][1], h0, l0);
                split2(acc[s][n][2], acc[s][n][3], h1, l1);
                *(uint32_t*)&Ch[(size_t)r0 * ldc + c0]       = h0;
                *(uint32_t*)&Cl[(size_t)r0 * ldc + c0]       = l0;
                *(uint32_t*)&Ch[(size_t)(r0 + 8) * ldc + c0] = h1;
                *(uint32_t*)&Cl[(size_t)(r0 + 8) * ldc + c0] = l1;
            }
        }
    }
}

// ============================================================================
// FLASH ATTENTION (R10 proven): fused QK^T -> online softmax -> P*V.
// ============================================================================
__global__ __launch_bounds__(256)
void flash_attn()
{
    int z = blockIdx.z;
    int b = z >> 4, h = z & 15;
    int qt = 15 - blockIdx.y;                 // heavy tiles first
    size_t qoff = ((size_t)(b * S_) + qt * 128) * D_ + h * HD_;
    size_t kvoff = (size_t)(b * S_) * D_ + h * HD_;
    const __nv_bfloat16* __restrict__ Qgh = g_Qh + qoff;
    const __nv_bfloat16* __restrict__ Qgl = g_Ql + qoff;
    const __nv_bfloat16* __restrict__ Kgh = g_Kh + kvoff;
    const __nv_bfloat16* __restrict__ Kgl = g_Kl + kvoff;
    const __nv_bfloat16* __restrict__ Vgh = g_Vh + kvoff;
    const __nv_bfloat16* __restrict__ Vgl = g_Vl + kvoff;
    __nv_bfloat16* __restrict__ AOh = g_AOh + qoff;
    __nv_bfloat16* __restrict__ AOl = g_AOl + qoff;

    extern __shared__ __align__(16) char sraw[];
    uint32_t sb  = smem_u32(sraw);
    uint32_t sQh = sb, sQl = sb + 32768u;

    int tid = threadIdx.x, lane = tid & 31, w = tid >> 5;
    int lr = lane & 7, grp = lane >> 3;

    #pragma unroll
    for (int i = 0; i < 8; i++) {
        int id = tid + (i << 8);
        int r = id >> 4, c = id & 15;
        uint32_t dst = sQh + ((uint32_t)r << 8) + (uint32_t)((c ^ (r & 7)) << 4);
        cpa16(dst,           Qgh + (size_t)r * D_ + (c << 3));
        cpa16(dst + 32768u,  Qgl + (size_t)r * D_ + (c << 3));
    }

    auto issueKV = [&](int kt, int stg) {
        uint32_t base = sb + 65536u + (uint32_t)stg * 65536u;
        #pragma unroll
        for (int i = 0; i < 4; i++) {
            int id = tid + (i << 8);
            int r = id >> 4, c = id & 15;
            uint32_t dst = base + ((uint32_t)r << 8) + (uint32_t)((c ^ (r & 7)) << 4);
            cpa16(dst,          Kgh + (size_t)(kt * 64 + r) * D_ + (c << 3));
            cpa16(dst + 16384u, Kgl + (size_t)(kt * 64 + r) * D_ + (c << 3));
            cpa16(dst + 32768u, Vgh + (size_t)(kt * 64 + r) * D_ + (c << 3));
            cpa16(dst + 49152u, Vgl + (size_t)(kt * 64 + r) * D_ + (c << 3));
        }
    };

    issueKV(0, 0);
    cpa_commit();

    int qr = 16 * w + ((grp & 1) << 3) + lr;
    uint32_t aoffBase = ((uint32_t)qr << 8);
    uint32_t aXor = qr & 7;

    uint32_t Ah[8][4];
    float accO[16][4];
    #pragma unroll
    for (int n = 0; n < 16; n++)
        #pragma unroll
        for (int j = 0; j < 4; j++) accO[n][j] = 0.f;
    float m0 = -1e30f, m1 = -1e30f, l0 = 0.f, l1 = 0.f;

    int row0 = qt * 128 + 16 * w + (lane >> 2);

    int T = 2 * qt + 2;
    for (int kt = 0; kt < T; kt++) {
        int stg = kt & 1;
        if (kt + 1 < T) { issueKV(kt + 1, stg ^ 1); cpa_commit(); cpa_wait<1>(); }
        else            { cpa_wait<0>(); }
        __syncthreads();

        if (kt == 0) {
            #pragma unroll
            for (int st = 0; st < 8; st++) {
                uint32_t off = aoffBase + ((((st << 1) + (grp >> 1)) ^ aXor) << 4);
                ldsm4(Ah[st], sQh + off);
            }
        }

        uint32_t base = sb + 65536u + (uint32_t)stg * 65536u;
        uint32_t sKh = base, sKl = base + 16384u, sVh = base + 32768u, sVl = base + 49152u;

        float accs[8][4];
        #pragma unroll
        for (int n = 0; n < 8; n++)
            #pragma unroll
            for (int j = 0; j < 4; j++) accs[n][j] = 0.f;

        #pragma unroll
        for (int st = 0; st < 8; st++) {
            uint32_t aL[4];
            {
                uint32_t off = aoffBase + ((((st << 1) + (grp >> 1)) ^ aXor) << 4);
                ldsm4(aL, sQl + off);
            }
            #pragma unroll
            for (int p = 0; p < 4; p++) {
                int rr = p * 16 + ((grp >> 1) << 3) + lr;
                uint32_t off = ((uint32_t)rr << 8) + ((((st << 1) + (grp & 1)) ^ (rr & 7)) << 4);
                uint32_t th[4], tl[4];
                ldsm4(th, sKh + off);
                ldsm4(tl, sKl + off);
                uint32_t f0[2] = {th[0], th[1]}, f1[2] = {th[2], th[3]};
                uint32_t g0[2] = {tl[0], tl[1]}, g1[2] = {tl[2], tl[3]};
                mma_bf16(accs[2*p],   Ah[st], f0);
                mma_bf16(accs[2*p],   Ah[st], g0);
                mma_bf16(accs[2*p],   aL,     f0);
                mma_bf16(accs[2*p+1], Ah[st], f1);
                mma_bf16(accs[2*p+1], Ah[st], g1);
                mma_bf16(accs[2*p+1], aL,     f1);
            }
        }

        if (kt >= 2 * qt) {
            int colb = kt * 64 + ((lane & 3) << 1);
            #pragma unroll
            for (int n = 0; n < 8; n++) {
                int c0 = colb + n * 8;
                if (c0     > row0)     accs[n][0] = -1e30f;
                if (c0 + 1 > row0)     accs[n][1] = -1e30f;
                if (c0     > row0 + 8) accs[n][2] = -1e30f;
                if (c0 + 1 > row0 + 8) accs[n][3] = -1e30f;
            }
        }

        float mx0 = -1e30f, mx1 = -1e30f;
        #pragma unroll
        for (int n = 0; n < 8; n++) {
            mx0 = fmaxf(mx0, fmaxf(accs[n][0], accs[n][1]));
            mx1 = fmaxf(mx1, fmaxf(accs[n][2], accs[n][3]));
        }
        mx0 = fmaxf(mx0, __shfl_xor_sync(0xffffffffu, mx0, 1));
        mx0 = fmaxf(mx0, __shfl_xor_sync(0xffffffffu, mx0, 2));
        mx1 = fmaxf(mx1, __shfl_xor_sync(0xffffffffu, mx1, 1));
        mx1 = fmaxf(mx1, __shfl_xor_sync(0xffffffffu, mx1, 2));
        float nm0 = fmaxf(m0, mx0), nm1 = fmaxf(m1, mx1);
        float sf0 = __expf(m0 - nm0), sf1 = __expf(m1 - nm1);
        m0 = nm0; m1 = nm1;

        float rs0 = 0.f, rs1 = 0.f;
        #pragma unroll
        for (int n = 0; n < 8; n++) {
            accs[n][0] = __expf(accs[n][0] - nm0); rs0 += accs[n][0];
            accs[n][1] = __expf(accs[n][1] - nm0); rs0 += accs[n][1];
            accs[n][2] = __expf(accs[n][2] - nm1); rs1 += accs[n][2];
            accs[n][3] = __expf(accs[n][3] - nm1); rs1 += accs[n][3];
        }
        rs0 += __shfl_xor_sync(0xffffffffu, rs0, 1);
        rs0 += __shfl_xor_sync(0xffffffffu, rs0, 2);
        rs1 += __shfl_xor_sync(0xffffffffu, rs1, 1);
        rs1 += __shfl_xor_sync(0xffffffffu, rs1, 2);
        l0 = l0 * sf0 + rs0;
        l1 = l1 * sf1 + rs1;

        #pragma unroll
        for (int n = 0; n < 16; n++) {
            accO[n][0] *= sf0; accO[n][1] *= sf0;
            accO[n][2] *= sf1; accO[n][3] *= sf1;
        }

        #pragma unroll
        for (int kp = 0; kp < 4; kp++) {
            uint32_t ph[4], pl[4];
            split2(accs[2*kp][0],   accs[2*kp][1],   ph[0], pl[0]);
            split2(accs[2*kp][2],   accs[2*kp][3],   ph[1], pl[1]);
            split2(accs[2*kp+1][0], accs[2*kp+1][1], ph[2], pl[2]);
            split2(accs[2*kp+1][2], accs[2*kp+1][3], ph[3], pl[3]);

            int krb = ((grp & 1) << 3) + lr;
            #pragma unroll
            for (int j = 0; j < 8; j++) {
                int nc = j * 2 + (grp >> 1);
                uint32_t off = ((uint32_t)kp << 12) + ((uint32_t)krb << 8)
                             + (uint32_t)((nc ^ (krb & 7)) << 4);
                uint32_t th[4], tl[4];
                ldsm4t(th, sVh + off);
                ldsm4t(tl, sVl + off);
                uint32_t f0[2] = {th[0], th[1]}, f1[2] = {th[2], th[3]};
                uint32_t g0[2] = {tl[0], tl[1]}, g1[2] = {tl[2], tl[3]};
                mma_bf16(accO[2*j],   ph, f0);
                mma_bf16(accO[2*j],   ph, g0);
                mma_bf16(accO[2*j],   pl, f0);
                mma_bf16(accO[2*j+1], ph, f1);
                mma_bf16(accO[2*j+1], ph, g1);
                mma_bf16(accO[2*j+1], pl, f1);
            }
        }
        __syncthreads();
    }

    float inv0 = 1.f / l0, inv1 = 1.f / l1;
    int lrow = 16 * w + (lane >> 2);
    #pragma unroll
    for (int n = 0; n < 16; n++) {
        int c0 = n * 8 + ((lane & 3) << 1);
        uint32_t h0, lo0, h1, lo1;
        split2(accO[n][0] * inv0, accO[n][1] * inv0, h0, lo0);
        split2(accO[n][2] * inv1, accO[n][3] * inv1, h1, lo1);
        *(uint32_t*)&AOh[(size_t)lrow * D_ + c0]       = h0;
        *(uint32_t*)&AOl[(size_t)lrow * D_ + c0]       = lo0;
        *(uint32_t*)&AOh[(size_t)(lrow + 8) * D_ + c0] = h1;
        *(uint32_t*)&AOl[(size_t)(lrow + 8) * D_ + c0] = lo1;
    }
}

// ---------------- RoPE tables -----------------------------------------------------
__global__ void rope_tables()
{
    int i = blockIdx.x * blockDim.x + threadIdx.x;
    if (i >= S_ * 64) return;
    int d = i & 63;
    int s = i >> 6;
    double inv = exp2(-(double)d / 64.0 * 13.287712379549449);   // log2(10000)
    double ang = (double)s * inv;
    g_cos[i] = (float)cos(ang);
    g_sin[i] = (float)sin(ang);
}

// ---------------- RoPE apply: fp32 Q/K -> split bf16 (scale folded into Q) -------
__global__ void rope_apply()
{
    size_t i = (size_t)blockIdx.x * blockDim.x + threadIdx.x;
    if (i >= (size_t)M_ * H_ * 64) return;
    int d = (int)(i & 63);
    int h = (int)((i >> 6) & (H_ - 1));
    int m = (int)(i >> 10);
    int s = m & (S_ - 1);
    float c  = g_cos[s * 64 + d];
    float sn = g_sin[s * 64 + d];
    const float scale = 0.08838834764831845f;   // 1/sqrt(128)
    size_t base = (size_t)m * D_ + h * HD_ + d;

    float q1 = g_Q[base], q2 = g_Q[base + 64];
    float qr1 = (q1 * c - q2 * sn) * scale;
    float qr2 = (q2 * c + q1 * sn) * scale;
    __nv_bfloat16 qh1 = __float2bfloat16(qr1);
    __nv_bfloat16 qh2 = __float2bfloat16(qr2);
    g_Qh[base]      = qh1; g_Ql[base]      = __float2bfloat16(qr1 - __bfloat162float(qh1));
    g_Qh[base + 64] = qh2; g_Ql[base + 64] = __float2bfloat16(qr2 - __bfloat162float(qh2));

    float k1 = g_K[base], k2 = g_K[base + 64];
    float kr1 = k1 * c - k2 * sn;
    float kr2 = k2 * c + k1 * sn;
    __nv_bfloat16 kh1 = __float2bfloat16(kr1);
    __nv_bfloat16 kh2 = __float2bfloat16(kr2);
    g_Kh[base]      = kh1; g_Kl[base]      = __float2bfloat16(kr1 - __bfloat162float(kh1));
    g_Kh[base + 64] = kh2; g_Kl[base + 64] = __float2bfloat16(kr2 - __bfloat162float(kh2));
}

// ---------------- launch ----------------------------------------------------------
extern "C" void kernel_launch(void* const* d_in, const int* in_sizes, int n_in,
                              void* d_out, int out_size)
{
    const float* x  = (const float*)d_in[0];
    const float* Wq = (const float*)d_in[1];
    const float* Wk = (const float*)d_in[2];
    const float* Wv = (const float*)d_in[3];
    const float* Wo = (const float*)d_in[4];
    float* out = (float*)d_out;

    float *Qp, *Kp;
    cudaGetSymbolAddress((void**)&Qp, g_Q);
    cudaGetSymbolAddress((void**)&Kp, g_K);
    __nv_bfloat16 *xh, *xl, *Wqh, *Wql, *Wkh, *Wkl, *Wvh, *Wvl, *Woh, *Wol;
    __nv_bfloat16 *Vh, *Vl, *AOh, *AOl;
    cudaGetSymbolAddress((void**)&xh,  g_xh);  cudaGetSymbolAddress((void**)&xl,  g_xl);
    cudaGetSymbolAddress((void**)&Wqh, g_Wqh); cudaGetSymbolAddress((void**)&Wql, g_Wql);
    cudaGetSymbolAddress((void**)&Wkh, g_Wkh); cudaGetSymbolAddress((void**)&Wkl, g_Wkl);
    cudaGetSymbolAddress((void**)&Wvh, g_Wvh); cudaGetSymbolAddress((void**)&Wvl, g_Wvl);
    cudaGetSymbolAddress((void**)&Woh, g_Woh); cudaGetSymbolAddress((void**)&Wol, g_Wol);
    cudaGetSymbolAddress((void**)&Vh,  g_Vh);  cudaGetSymbolAddress((void**)&Vl,  g_Vl);
    cudaGetSymbolAddress((void**)&AOh, g_AOh); cudaGetSymbolAddress((void**)&AOl, g_AOl);

    cudaFuncSetAttribute(gemm_big,   cudaFuncAttributeMaxDynamicSharedMemorySize, 196608);
    cudaFuncSetAttribute(flash_attn, cudaFuncAttributeMaxDynamicSharedMemorySize, 196608);

    dim3 blk256(256);

    // 0) split inputs
    {
        int n4x = (int)((size_t)M_ * D_ / 4);
        int n4w = (int)((size_t)D_ * D_ / 4);
        split_arr<<<(n4x + 255) / 256, blk256>>>((const float4*)x,  (uint2*)xh,  (uint2*)xl,  n4x);
        split_arr<<<(n4w + 255) / 256, blk256>>>((const float4*)Wq, (uint2*)Wqh, (uint2*)Wql, n4w);
        split_arr<<<(n4w + 255) / 256, blk256>>>((const float4*)Wk, (uint2*)Wkh, (uint2*)Wkl, n4w);
        split_arr<<<(n4w + 255) / 256, blk256>>>((const float4*)Wv, (uint2*)Wvh, (uint2*)Wvl, n4w);
        split_arr<<<(n4w + 255) / 256, blk256>>>((const float4*)Wo, (uint2*)Woh, (uint2*)Wol, n4w);
    }

    // 1) projections (big-tile): Q,K fp32 (rope follows) ; V split direct
    dim3 gProj(D_ / 128, M_ / 256, 1);
    gemm_big<<<gProj, blk256, 196608>>>(xh, xl, Wqh, Wql, Qp, 0, 0,
                                        D_, D_, D_, D_, 0);
    gemm_big<<<gProj, blk256, 196608>>>(xh, xl, Wkh, Wkl, Kp, 0, 0,
                                        D_, D_, D_, D_, 0);
    gemm_big<<<gProj, blk256, 196608>>>(xh, xl, Wvh, Wvl, 0, Vh, Vl,
                                        D_, D_, D_, D_, 1);

    // 2) RoPE
    rope_tables<<<(S_ * 64 + 255) / 256, blk256>>>();
    rope_apply<<<((size_t)M_ * H_ * 64 + 255) / 256, blk256>>>();

    // 3) fused attention: QK^T + online softmax + P*V
    dim3 gF(1, S_ / 128, B_ * H_);
    flash_attn<<<gF, blk256, 196608>>>();

    // 4) out = AO * Wo^T (big-tile), fp32 out
    gemm_big<<<gProj, blk256, 196608>>>(AOh, AOl, Woh, Wol, out, 0, 0,
                                        D_, D_, D_, D_, 0);
}

// round 13
// speedup vs baseline: 1.3498x; 1.3498x over previous
#include <cuda_runtime.h>
#include <cuda_bf16.h>
#include <math.h>
#include <stdint.h>

#define B_  2
#define S_  2048
#define D_  2048
#define H_  16
#define HD_ 128
#define M_  (B_*S_)      // 4096 rows total

// ---------------- scratch (device globals; no allocation allowed) ----------------
__device__ float g_Q[(size_t)M_*D_];                 // fp32 proj out (pre-rope)
__device__ float g_K[(size_t)M_*D_];
__device__ float g_cos[S_*64];
__device__ float g_sin[S_*64];

__device__ __nv_bfloat16 g_xh[(size_t)M_*D_],  g_xl[(size_t)M_*D_];
__device__ __nv_bfloat16 g_Wqh[(size_t)D_*D_], g_Wql[(size_t)D_*D_];
__device__ __nv_bfloat16 g_Wkh[(size_t)D_*D_], g_Wkl[(size_t)D_*D_];
__device__ __nv_bfloat16 g_Wvh[(size_t)D_*D_], g_Wvl[(size_t)D_*D_];
__device__ __nv_bfloat16 g_Woh[(size_t)D_*D_], g_Wol[(size_t)D_*D_];
__device__ __nv_bfloat16 g_Qh[(size_t)M_*D_],  g_Ql[(size_t)M_*D_];
__device__ __nv_bfloat16 g_Kh[(size_t)M_*D_],  g_Kl[(size_t)M_*D_];
__device__ __nv_bfloat16 g_Vh[(size_t)M_*D_],  g_Vl[(size_t)M_*D_];
__device__ __nv_bfloat16 g_AOh[(size_t)M_*D_], g_AOl[(size_t)M_*D_];

// ---------------- helpers ---------------------------------------------------------
__device__ __forceinline__ uint32_t smem_u32(const void* p) {
    return (uint32_t)__cvta_generic_to_shared(p);
}
__device__ __forceinline__ void cpa16(uint32_t dst, const void* src) {
    asm volatile("cp.async.cg.shared.global [%0],[%1],16;" :: "r"(dst), "l"(src));
}
__device__ __forceinline__ void cpa_commit() { asm volatile("cp.async.commit_group;"); }
template<int N> __device__ __forceinline__ void cpa_wait() {
    asm volatile("cp.async.wait_group %0;" :: "n"(N));
}
__device__ __forceinline__ void ldsm4(uint32_t r[4], uint32_t addr) {
    asm volatile("ldmatrix.sync.aligned.m8n8.x4.shared.b16 {%0,%1,%2,%3},[%4];"
                 : "=r"(r[0]), "=r"(r[1]), "=r"(r[2]), "=r"(r[3]) : "r"(addr));
}
__device__ __forceinline__ void ldsm4t(uint32_t r[4], uint32_t addr) {
    asm volatile("ldmatrix.sync.aligned.m8n8.x4.trans.shared.b16 {%0,%1,%2,%3},[%4];"
                 : "=r"(r[0]), "=r"(r[1]), "=r"(r[2]), "=r"(r[3]) : "r"(addr));
}
__device__ __forceinline__ void mma_bf16(float d[4], const uint32_t a[4], const uint32_t b[2]) {
    asm volatile(
        "mma.sync.aligned.m16n8k16.row.col.f32.bf16.bf16.f32 "
        "{%0,%1,%2,%3},{%4,%5,%6,%7},{%8,%9},{%0,%1,%2,%3};"
        : "+f"(d[0]), "+f"(d[1]), "+f"(d[2]), "+f"(d[3])
        : "r"(a[0]), "r"(a[1]), "r"(a[2]), "r"(a[3]), "r"(b[0]), "r"(b[1]));
}
__device__ __forceinline__ void split2(float x0, float x1, uint32_t &h, uint32_t &l) {
    __nv_bfloat16 h0 = __float2bfloat16(x0);
    __nv_bfloat16 h1 = __float2bfloat16(x1);
    __nv_bfloat16 l0 = __float2bfloat16(x0 - __bfloat162float(h0));
    __nv_bfloat16 l1 = __float2bfloat16(x1 - __bfloat162float(h1));
    __nv_bfloat162 hp = __halves2bfloat162(h0, h1);
    __nv_bfloat162 lp = __halves2bfloat162(l0, l1);
    h = *reinterpret_cast<uint32_t*>(&hp);
    l = *reinterpret_cast<uint32_t*>(&lp);
}

// ---------------- elementwise fp32 -> (hi,lo) convert -----------------------------
__global__ __launch_bounds__(256)
void split_arr(const float4* __restrict__ src,
               uint2* __restrict__ h, uint2* __restrict__ l, int n4)
{
    int i = blockIdx.x * blockDim.x + threadIdx.x;
    if (i >= n4) return;
    float4 v = src[i];
    uint32_t h0, l0, h1, l1;
    split2(v.x, v.y, h0, l0);
    split2(v.z, v.w, h1, l1);
    h[i] = make_uint2(h0, h1);
    l[i] = make_uint2(l0, l1);
}

// ============================================================================
// BIG-TILE projection GEMM: C = A * B^T, 256x128 CTA, half-stage (k32)
// pipeline, ring = 2 stages x 2 halves, 3 halves in flight.
// COALESCED loader: 4 threads per row, 64B contiguous segments.
// 256 threads, 8 warps 4m x 2n, warp tile 64x64. smem 192KB.
// outSplit: 0 -> C fp32 ; 1 -> Ch/Cl bf16.
// ============================================================================
__global__ __launch_bounds__(256)
void gemm_big(const __nv_bfloat16* __restrict__ Agh, const __nv_bfloat16* __restrict__ Agl,
              const __nv_bfloat16* __restrict__ Bgh, const __nv_bfloat16* __restrict__ Bgl,
              float* __restrict__ C,
              __nv_bfloat16* __restrict__ Ch, __nv_bfloat16* __restrict__ Cl,
              int K, int lda, int ldb, int ldc, int outSplit)
{
    int rowBase = blockIdx.y * 256;
    int colBase = blockIdx.x * 128;

    extern __shared__ __align__(16) char sraw[];
    uint32_t sb = smem_u32(sraw);

    int tid = threadIdx.x, lane = tid & 31, w = tid >> 5;
    int wm = w >> 1, wn = w & 1;
    int lr = lane & 7, grp = lane >> 3;

    int agk = grp >> 1;
    uint32_t arow[4], arx[4];
    #pragma unroll
    for (int s = 0; s < 4; s++) {
        int r = wm * 64 + s * 16 + ((grp & 1) << 3) + lr;
        arow[s] = (uint32_t)r << 7;
        arx[s]  = r & 7;
    }
    int bgk = grp & 1;
    uint32_t brow[4], brx[4];
    #pragma unroll
    for (int p = 0; p < 4; p++) {
        int r = wn * 64 + p * 16 + ((grp >> 1) << 3) + lr;
        brow[p] = (uint32_t)r << 7;
        brx[p]  = r & 7;
    }

    float acc[4][8][4];
    #pragma unroll
    for (int s = 0; s < 4; s++)
        #pragma unroll
        for (int n = 0; n < 8; n++)
            #pragma unroll
            for (int j = 0; j < 4; j++) acc[s][n][j] = 0.f;

    int T2 = K >> 5;                      // half-stages (k32 each)

    // half-stage = chunks [hf*4, hf*4+4). A: 256 rows x 4 chunks (4 thr/row),
    // B: 128 rows x 4 chunks. 64B contiguous per row-visit -> coalesced.
    auto issueHalf = [&](int u) {
        int stg = (u >> 1) & 1;
        int hf  = u & 1;
        uint32_t base = sb + (uint32_t)stg * 98304u;
        int k0 = (u >> 1) << 6;
        #pragma unroll
        for (int i = 0; i < 4; i++) {
            int id = tid + (i << 8);
            int r = id >> 2;
            int c = (id & 3) | (hf << 2);
            uint32_t dst = base + ((uint32_t)r << 7) + (uint32_t)((c ^ (r & 7)) << 4);
            cpa16(dst,           Agh + (size_t)(rowBase + r) * lda + k0 + (c << 3));
            cpa16(dst + 32768u,  Agl + (size_t)(rowBase + r) * lda + k0 + (c << 3));
        }
        #pragma unroll
        for (int i = 0; i < 2; i++) {
            int id = tid + (i << 8);
            int r = id >> 2;
            int c = (id & 3) | (hf << 2);
            uint32_t dst = base + 65536u + ((uint32_t)r << 7) + (uint32_t)((c ^ (r & 7)) << 4);
            cpa16(dst,           Bgh + (size_t)(colBase + r) * ldb + k0 + (c << 3));
            cpa16(dst + 16384u,  Bgl + (size_t)(colBase + r) * ldb + k0 + (c << 3));
        }
        cpa_commit();
    };

    issueHalf(0);
    if (T2 > 1) issueHalf(1);
    if (T2 > 2) issueHalf(2);

    for (int u = 0; u < T2; u++) {
        if (u < T2 - 2)      cpa_wait<2>();
        else if (u == T2 - 2) cpa_wait<1>();
        else                  cpa_wait<0>();
        __syncthreads();
        if (u + 3 < T2) issueHalf(u + 3);

        int stg = (u >> 1) & 1;
        int hf  = u & 1;
        uint32_t aH = sb + (uint32_t)stg * 98304u;
        uint32_t aL = aH + 32768u;
        uint32_t bH = aH + 65536u;
        uint32_t bL = aH + 81920u;

        #pragma unroll
        for (int st2 = 0; st2 < 2; st2++) {
            int st = (hf << 1) + st2;
            uint32_t Ah[4][4], Al[4][4], Bh[8][2], Bl[8][2];
            #pragma unroll
            for (int s = 0; s < 4; s++) {
                uint32_t off = arow[s] + ((((st << 1) + agk) ^ arx[s]) << 4);
                ldsm4(Ah[s], aH + off);
                ldsm4(Al[s], aL + off);
            }
            #pragma unroll
            for (int p = 0; p < 4; p++) {
                uint32_t off = brow[p] + ((((st << 1) + bgk) ^ brx[p]) << 4);
                uint32_t tr[4];
                ldsm4(tr, bH + off);
                Bh[2*p][0] = tr[0]; Bh[2*p][1] = tr[1];
                Bh[2*p+1][0] = tr[2]; Bh[2*p+1][1] = tr[3];
                ldsm4(tr, bL + off);
                Bl[2*p][0] = tr[0]; Bl[2*p][1] = tr[1];
                Bl[2*p+1][0] = tr[2]; Bl[2*p+1][1] = tr[3];
            }
            #pragma unroll
            for (int s = 0; s < 4; s++)
                #pragma unroll
                for (int n = 0; n < 8; n++) {
                    mma_bf16(acc[s][n], Ah[s], Bh[n]);
                    mma_bf16(acc[s][n], Ah[s], Bl[n]);
                    mma_bf16(acc[s][n], Al[s], Bh[n]);
                }
        }
    }

    __syncthreads();
    #pragma unroll
    for (int s = 0; s < 4; s++) {
        int r0 = rowBase + wm * 64 + s * 16 + (lane >> 2);
        #pragma unroll
        for (int n = 0; n < 8; n++) {
            int c0 = colBase + wn * 64 + n * 8 + ((lane & 3) << 1);
            if (!outSplit) {
                *(float2*)&C[(size_t)r0 * ldc + c0]       = make_float2(acc[s][n][0], acc[s][n][1]);
                *(float2*)&C[(size_t)(r0 + 8) * ldc + c0] = make_float2(acc[s][n][2], acc[s][n][3]);
            } else {
                uint32_t h0, l0, h1, l1;
                split2(acc[s][n][0], acc[s][n][1], h0, l0);
                split2(acc[s][n][2], acc[s][n][3], h1, l1);
                *(uint32_t*)&Ch[(size_t)r0 * ldc + c0]       = h0;
                *(uint32_t*)&Cl[(size_t)r0 * ldc + c0]       = l0;
                *(uint32_t*)&Ch[(size_t)(r0 + 8) * ldc + c0] = h1;
                *(uint32_t*)&Cl[(size_t)(r0 + 8) * ldc + c0] = l1;
            }
        }
    }
}

// ============================================================================
// FLASH ATTENTION (R10 proven): fused QK^T -> online softmax -> P*V.
// ============================================================================
__global__ __launch_bounds__(256)
void flash_attn()
{
    int z = blockIdx.z;
    int b = z >> 4, h = z & 15;
    int qt = 15 - blockIdx.y;                 // heavy tiles first
    size_t qoff = ((size_t)(b * S_) + qt * 128) * D_ + h * HD_;
    size_t kvoff = (size_t)(b * S_) * D_ + h * HD_;
    const __nv_bfloat16* __restrict__ Qgh = g_Qh + qoff;
    const __nv_bfloat16* __restrict__ Qgl = g_Ql + qoff;
    const __nv_bfloat16* __restrict__ Kgh = g_Kh + kvoff;
    const __nv_bfloat16* __restrict__ Kgl = g_Kl + kvoff;
    const __nv_bfloat16* __restrict__ Vgh = g_Vh + kvoff;
    const __nv_bfloat16* __restrict__ Vgl = g_Vl + kvoff;
    __nv_bfloat16* __restrict__ AOh = g_AOh + qoff;
    __nv_bfloat16* __restrict__ AOl = g_AOl + qoff;

    extern __shared__ __align__(16) char sraw[];
    uint32_t sb  = smem_u32(sraw);
    uint32_t sQh = sb, sQl = sb + 32768u;

    int tid = threadIdx.x, lane = tid & 31, w = tid >> 5;
    int lr = lane & 7, grp = lane >> 3;

    #pragma unroll
    for (int i = 0; i < 8; i++) {
        int id = tid + (i << 8);
        int r = id >> 4, c = id & 15;
        uint32_t dst = sQh + ((uint32_t)r << 8) + (uint32_t)((c ^ (r & 7)) << 4);
        cpa16(dst,           Qgh + (size_t)r * D_ + (c << 3));
        cpa16(dst + 32768u,  Qgl + (size_t)r * D_ + (c << 3));
    }

    auto issueKV = [&](int kt, int stg) {
        uint32_t base = sb + 65536u + (uint32_t)stg * 65536u;
        #pragma unroll
        for (int i = 0; i < 4; i++) {
            int id = tid + (i << 8);
            int r = id >> 4, c = id & 15;
            uint32_t dst = base + ((uint32_t)r << 8) + (uint32_t)((c ^ (r & 7)) << 4);
            cpa16(dst,          Kgh + (size_t)(kt * 64 + r) * D_ + (c << 3));
            cpa16(dst + 16384u, Kgl + (size_t)(kt * 64 + r) * D_ + (c << 3));
            cpa16(dst + 32768u, Vgh + (size_t)(kt * 64 + r) * D_ + (c << 3));
            cpa16(dst + 49152u, Vgl + (size_t)(kt * 64 + r) * D_ + (c << 3));
        }
    };

    issueKV(0, 0);
    cpa_commit();

    int qr = 16 * w + ((grp & 1) << 3) + lr;
    uint32_t aoffBase = ((uint32_t)qr << 8);
    uint32_t aXor = qr & 7;

    uint32_t Ah[8][4];
    float accO[16][4];
    #pragma unroll
    for (int n = 0; n < 16; n++)
        #pragma unroll
        for (int j = 0; j < 4; j++) accO[n][j] = 0.f;
    float m0 = -1e30f, m1 = -1e30f, l0 = 0.f, l1 = 0.f;

    int row0 = qt * 128 + 16 * w + (lane >> 2);

    int T = 2 * qt + 2;
    for (int kt = 0; kt < T; kt++) {
        int stg = kt & 1;
        if (kt + 1 < T) { issueKV(kt + 1, stg ^ 1); cpa_commit(); cpa_wait<1>(); }
        else            { cpa_wait<0>(); }
        __syncthreads();

        if (kt == 0) {
            #pragma unroll
            for (int st = 0; st < 8; st++) {
                uint32_t off = aoffBase + ((((st << 1) + (grp >> 1)) ^ aXor) << 4);
                ldsm4(Ah[st], sQh + off);
            }
        }

        uint32_t base = sb + 65536u + (uint32_t)stg * 65536u;
        uint32_t sKh = base, sKl = base + 16384u, sVh = base + 32768u, sVl = base + 49152u;

        float accs[8][4];
        #pragma unroll
        for (int n = 0; n < 8; n++)
            #pragma unroll
            for (int j = 0; j < 4; j++) accs[n][j] = 0.f;

        #pragma unroll
        for (int st = 0; st < 8; st++) {
            uint32_t aL[4];
            {
                uint32_t off = aoffBase + ((((st << 1) + (grp >> 1)) ^ aXor) << 4);
                ldsm4(aL, sQl + off);
            }
            #pragma unroll
            for (int p = 0; p < 4; p++) {
                int rr = p * 16 + ((grp >> 1) << 3) + lr;
                uint32_t off = ((uint32_t)rr << 8) + ((((st << 1) + (grp & 1)) ^ (rr & 7)) << 4);
                uint32_t th[4], tl[4];
                ldsm4(th, sKh + off);
                ldsm4(tl, sKl + off);
                uint32_t f0[2] = {th[0], th[1]}, f1[2] = {th[2], th[3]};
                uint32_t g0[2] = {tl[0], tl[1]}, g1[2] = {tl[2], tl[3]};
                mma_bf16(accs[2*p],   Ah[st], f0);
                mma_bf16(accs[2*p],   Ah[st], g0);
                mma_bf16(accs[2*p],   aL,     f0);
                mma_bf16(accs[2*p+1], Ah[st], f1);
                mma_bf16(accs[2*p+1], Ah[st], g1);
                mma_bf16(accs[2*p+1], aL,     f1);
            }
        }

        if (kt >= 2 * qt) {
            int colb = kt * 64 + ((lane & 3) << 1);
            #pragma unroll
            for (int n = 0; n < 8; n++) {
                int c0 = colb + n * 8;
                if (c0     > row0)     accs[n][0] = -1e30f;
                if (c0 + 1 > row0)     accs[n][1] = -1e30f;
                if (c0     > row0 + 8) accs[n][2] = -1e30f;
                if (c0 + 1 > row0 + 8) accs[n][3] = -1e30f;
            }
        }

        float mx0 = -1e30f, mx1 = -1e30f;
        #pragma unroll
        for (int n = 0; n < 8; n++) {
            mx0 = fmaxf(mx0, fmaxf(accs[n][0], accs[n][1]));
            mx1 = fmaxf(mx1, fmaxf(accs[n][2], accs[n][3]));
        }
        mx0 = fmaxf(mx0, __shfl_xor_sync(0xffffffffu, mx0, 1));
        mx0 = fmaxf(mx0, __shfl_xor_sync(0xffffffffu, mx0, 2));
        mx1 = fmaxf(mx1, __shfl_xor_sync(0xffffffffu, mx1, 1));
        mx1 = fmaxf(mx1, __shfl_xor_sync(0xffffffffu, mx1, 2));
        float nm0 = fmaxf(m0, mx0), nm1 = fmaxf(m1, mx1);
        float sf0 = __expf(m0 - nm0), sf1 = __expf(m1 - nm1);
        m0 = nm0; m1 = nm1;

        float rs0 = 0.f, rs1 = 0.f;
        #pragma unroll
        for (int n = 0; n < 8; n++) {
            accs[n][0] = __expf(accs[n][0] - nm0); rs0 += accs[n][0];
            accs[n][1] = __expf(accs[n][1] - nm0); rs0 += accs[n][1];
            accs[n][2] = __expf(accs[n][2] - nm1); rs1 += accs[n][2];
            accs[n][3] = __expf(accs[n][3] - nm1); rs1 += accs[n][3];
        }
        rs0 += __shfl_xor_sync(0xffffffffu, rs0, 1);
        rs0 += __shfl_xor_sync(0xffffffffu, rs0, 2);
        rs1 += __shfl_xor_sync(0xffffffffu, rs1, 1);
        rs1 += __shfl_xor_sync(0xffffffffu, rs1, 2);
        l0 = l0 * sf0 + rs0;
        l1 = l1 * sf1 + rs1;

        #pragma unroll
        for (int n = 0; n < 16; n++) {
            accO[n][0] *= sf0; accO[n][1] *= sf0;
            accO[n][2] *= sf1; accO[n][3] *= sf1;
        }

        #pragma unroll
        for (int kp = 0; kp < 4; kp++) {
            uint32_t ph[4], pl[4];
            split2(accs[2*kp][0],   accs[2*kp][1],   ph[0], pl[0]);
            split2(accs[2*kp][2],   accs[2*kp][3],   ph[1], pl[1]);
            split2(accs[2*kp+1][0], accs[2*kp+1][1], ph[2], pl[2]);
            split2(accs[2*kp+1][2], accs[2*kp+1][3], ph[3], pl[3]);

            int krb = ((grp & 1) << 3) + lr;
            #pragma unroll
            for (int j = 0; j < 8; j++) {
                int nc = j * 2 + (grp >> 1);
                uint32_t off = ((uint32_t)kp << 12) + ((uint32_t)krb << 8)
                             + (uint32_t)((nc ^ (krb & 7)) << 4);
                uint32_t th[4], tl[4];
                ldsm4t(th, sVh + off);
                ldsm4t(tl, sVl + off);
                uint32_t f0[2] = {th[0], th[1]}, f1[2] = {th[2], th[3]};
                uint32_t g0[2] = {tl[0], tl[1]}, g1[2] = {tl[2], tl[3]};
                mma_bf16(accO[2*j],   ph, f0);
                mma_bf16(accO[2*j],   ph, g0);
                mma_bf16(accO[2*j],   pl, f0);
                mma_bf16(accO[2*j+1], ph, f1);
                mma_bf16(accO[2*j+1], ph, g1);
                mma_bf16(accO[2*j+1], pl, f1);
            }
        }
        __syncthreads();
    }

    float inv0 = 1.f / l0, inv1 = 1.f / l1;
    int lrow = 16 * w + (lane >> 2);
    #pragma unroll
    for (int n = 0; n < 16; n++) {
        int c0 = n * 8 + ((lane & 3) << 1);
        uint32_t h0, lo0, h1, lo1;
        split2(accO[n][0] * inv0, accO[n][1] * inv0, h0, lo0);
        split2(accO[n][2] * inv1, accO[n][3] * inv1, h1, lo1);
        *(uint32_t*)&AOh[(size_t)lrow * D_ + c0]       = h0;
        *(uint32_t*)&AOl[(size_t)lrow * D_ + c0]       = lo0;
        *(uint32_t*)&AOh[(size_t)(lrow + 8) * D_ + c0] = h1;
        *(uint32_t*)&AOl[(size_t)(lrow + 8) * D_ + c0] = lo1;
    }
}

// ---------------- RoPE tables -----------------------------------------------------
__global__ void rope_tables()
{
    int i = blockIdx.x * blockDim.x + threadIdx.x;
    if (i >= S_ * 64) return;
    int d = i & 63;
    int s = i >> 6;
    double inv = exp2(-(double)d / 64.0 * 13.287712379549449);   // log2(10000)
    double ang = (double)s * inv;
    g_cos[i] = (float)cos(ang);
    g_sin[i] = (float)sin(ang);
}

// ---------------- RoPE apply: fp32 Q/K -> split bf16 (scale folded into Q) -------
__global__ void rope_apply()
{
    size_t i = (size_t)blockIdx.x * blockDim.x + threadIdx.x;
    if (i >= (size_t)M_ * H_ * 64) return;
    int d = (int)(i & 63);
    int h = (int)((i >> 6) & (H_ - 1));
    int m = (int)(i >> 10);
    int s = m & (S_ - 1);
    float c  = g_cos[s * 64 + d];
    float sn = g_sin[s * 64 + d];
    const float scale = 0.08838834764831845f;   // 1/sqrt(128)
    size_t base = (size_t)m * D_ + h * HD_ + d;

    float q1 = g_Q[base], q2 = g_Q[base + 64];
    float qr1 = (q1 * c - q2 * sn) * scale;
    float qr2 = (q2 * c + q1 * sn) * scale;
    __nv_bfloat16 qh1 = __float2bfloat16(qr1);
    __nv_bfloat16 qh2 = __float2bfloat16(qr2);
    g_Qh[base]      = qh1; g_Ql[base]      = __float2bfloat16(qr1 - __bfloat162float(qh1));
    g_Qh[base + 64] = qh2; g_Ql[base + 64] = __float2bfloat16(qr2 - __bfloat162float(qh2));

    float k1 = g_K[base], k2 = g_K[base + 64];
    float kr1 = k1 * c - k2 * sn;
    float kr2 = k2 * c + k1 * sn;
    __nv_bfloat16 kh1 = __float2bfloat16(kr1);
    __nv_bfloat16 kh2 = __float2bfloat16(kr2);
    g_Kh[base]      = kh1; g_Kl[base]      = __float2bfloat16(kr1 - __bfloat162float(kh1));
    g_Kh[base + 64] = kh2; g_Kl[base + 64] = __float2bfloat16(kr2 - __bfloat162float(kh2));
}

// ---------------- launch ----------------------------------------------------------
extern "C" void kernel_launch(void* const* d_in, const int* in_sizes, int n_in,
                              void* d_out, int out_size)
{
    const float* x  = (const float*)d_in[0];
    const float* Wq = (const float*)d_in[1];
    const float* Wk = (const float*)d_in[2];
    const float* Wv = (const float*)d_in[3];
    const float* Wo = (const float*)d_in[4];
    float* out = (float*)d_out;

    float *Qp, *Kp;
    cudaGetSymbolAddress((void**)&Qp, g_Q);
    cudaGetSymbolAddress((void**)&Kp, g_K);
    __nv_bfloat16 *xh, *xl, *Wqh, *Wql, *Wkh, *Wkl, *Wvh, *Wvl, *Woh, *Wol;
    __nv_bfloat16 *Vh, *Vl, *AOh, *AOl;
    cudaGetSymbolAddress((void**)&xh,  g_xh);  cudaGetSymbolAddress((void**)&xl,  g_xl);
    cudaGetSymbolAddress((void**)&Wqh, g_Wqh); cudaGetSymbolAddress((void**)&Wql, g_Wql);
    cudaGetSymbolAddress((void**)&Wkh, g_Wkh); cudaGetSymbolAddress((void**)&Wkl, g_Wkl);
    cudaGetSymbolAddress((void**)&Wvh, g_Wvh); cudaGetSymbolAddress((void**)&Wvl, g_Wvl);
    cudaGetSymbolAddress((void**)&Woh, g_Woh); cudaGetSymbolAddress((void**)&Wol, g_Wol);
    cudaGetSymbolAddress((void**)&Vh,  g_Vh);  cudaGetSymbolAddress((void**)&Vl,  g_Vl);
    cudaGetSymbolAddress((void**)&AOh, g_AOh); cudaGetSymbolAddress((void**)&AOl, g_AOl);

    cudaFuncSetAttribute(gemm_big,   cudaFuncAttributeMaxDynamicSharedMemorySize, 196608);
    cudaFuncSetAttribute(flash_attn, cudaFuncAttributeMaxDynamicSharedMemorySize, 196608);

    dim3 blk256(256);

    // 0) split inputs
    {
        int n4x = (int)((size_t)M_ * D_ / 4);
        int n4w = (int)((size_t)D_ * D_ / 4);
        split_arr<<<(n4x + 255) / 256, blk256>>>((const float4*)x,  (uint2*)xh,  (uint2*)xl,  n4x);
        split_arr<<<(n4w + 255) / 256, blk256>>>((const float4*)Wq, (uint2*)Wqh, (uint2*)Wql, n4w);
        split_arr<<<(n4w + 255) / 256, blk256>>>((const float4*)Wk, (uint2*)Wkh, (uint2*)Wkl, n4w);
        split_arr<<<(n4w + 255) / 256, blk256>>>((const float4*)Wv, (uint2*)Wvh, (uint2*)Wvl, n4w);
        split_arr<<<(n4w + 255) / 256, blk256>>>((const float4*)Wo, (uint2*)Woh, (uint2*)Wol, n4w);
    }

    // 1) projections (big-tile): Q,K fp32 (rope follows) ; V split direct
    dim3 gProj(D_ / 128, M_ / 256, 1);
    gemm_big<<<gProj, blk256, 196608>>>(xh, xl, Wqh, Wql, Qp, 0, 0,
                                        D_, D_, D_, D_, 0);
    gemm_big<<<gProj, blk256, 196608>>>(xh, xl, Wkh, Wkl, Kp, 0, 0,
                                        D_, D_, D_, D_, 0);
    gemm_big<<<gProj, blk256, 196608>>>(xh, xl, Wvh, Wvl, 0, Vh, Vl,
                                        D_, D_, D_, D_, 1);

    // 2) RoPE
    rope_tables<<<(S_ * 64 + 255) / 256, blk256>>>();
    rope_apply<<<((size_t)M_ * H_ * 64 + 255) / 256, blk256>>>();

    // 3) fused attention: QK^T + online softmax + P*V
    dim3 gF(1, S_ / 128, B_ * H_);
    flash_attn<<<gF, blk256, 196608>>>();

    // 4) out = AO * Wo^T (big-tile), fp32 out
    gemm_big<<<gProj, blk256, 196608>>>(AOh, AOl, Woh, Wol, out, 0, 0,
                                        D_, D_, D_, D_, 0);
}

// round 14
// speedup vs baseline: 2.6061x; 1.9308x over previous
#include <cuda_runtime.h>
#include <cuda_bf16.h>
#include <cuda_fp16.h>
#include <math.h>
#include <stdint.h>

#define B_  2
#define S_  2048
#define D_  2048
#define H_  16
#define HD_ 128
#define M_  (B_*S_)      // 4096 rows total

// ---------------- scratch (device globals; no allocation allowed) ----------------
__device__ float g_Q[(size_t)M_*D_];                 // fp32 proj out (pre-rope)
__device__ float g_K[(size_t)M_*D_];
__device__ float g_cos[S_*64];
__device__ float g_sin[S_*64];

__device__ __half g_xf[(size_t)M_*D_];
__device__ __half g_Wqf[(size_t)D_*D_];
__device__ __half g_Wkf[(size_t)D_*D_];
__device__ __half g_Wvf[(size_t)D_*D_];
__device__ __half g_Wof[(size_t)D_*D_];
__device__ __half g_AOf[(size_t)M_*D_];

__device__ __nv_bfloat16 g_Qh[(size_t)M_*D_],  g_Ql[(size_t)M_*D_];
__device__ __nv_bfloat16 g_Kh[(size_t)M_*D_],  g_Kl[(size_t)M_*D_];
__device__ __nv_bfloat16 g_Vh[(size_t)M_*D_],  g_Vl[(size_t)M_*D_];

// ---------------- helpers ---------------------------------------------------------
__device__ __forceinline__ uint32_t smem_u32(const void* p) {
    return (uint32_t)__cvta_generic_to_shared(p);
}
__device__ __forceinline__ void cpa16(uint32_t dst, const void* src) {
    asm volatile("cp.async.cg.shared.global [%0],[%1],16;" :: "r"(dst), "l"(src));
}
__device__ __forceinline__ void cpa_commit() { asm volatile("cp.async.commit_group;"); }
template<int N> __device__ __forceinline__ void cpa_wait() {
    asm volatile("cp.async.wait_group %0;" :: "n"(N));
}
__device__ __forceinline__ void ldsm4(uint32_t r[4], uint32_t addr) {
    asm volatile("ldmatrix.sync.aligned.m8n8.x4.shared.b16 {%0,%1,%2,%3},[%4];"
                 : "=r"(r[0]), "=r"(r[1]), "=r"(r[2]), "=r"(r[3]) : "r"(addr));
}
__device__ __forceinline__ void ldsm4t(uint32_t r[4], uint32_t addr) {
    asm volatile("ldmatrix.sync.aligned.m8n8.x4.trans.shared.b16 {%0,%1,%2,%3},[%4];"
                 : "=r"(r[0]), "=r"(r[1]), "=r"(r[2]), "=r"(r[3]) : "r"(addr));
}
__device__ __forceinline__ void mma_bf16(float d[4], const uint32_t a[4], const uint32_t b[2]) {
    asm volatile(
        "mma.sync.aligned.m16n8k16.row.col.f32.bf16.bf16.f32 "
        "{%0,%1,%2,%3},{%4,%5,%6,%7},{%8,%9},{%0,%1,%2,%3};"
        : "+f"(d[0]), "+f"(d[1]), "+f"(d[2]), "+f"(d[3])
        : "r"(a[0]), "r"(a[1]), "r"(a[2]), "r"(a[3]), "r"(b[0]), "r"(b[1]));
}
__device__ __forceinline__ void mma_fp16(float d[4], const uint32_t a[4], const uint32_t b[2]) {
    asm volatile(
        "mma.sync.aligned.m16n8k16.row.col.f32.f16.f16.f32 "
        "{%0,%1,%2,%3},{%4,%5,%6,%7},{%8,%9},{%0,%1,%2,%3};"
        : "+f"(d[0]), "+f"(d[1]), "+f"(d[2]), "+f"(d[3])
        : "r"(a[0]), "r"(a[1]), "r"(a[2]), "r"(a[3]), "r"(b[0]), "r"(b[1]));
}
__device__ __forceinline__ void split2(float x0, float x1, uint32_t &h, uint32_t &l) {
    __nv_bfloat16 h0 = __float2bfloat16(x0);
    __nv_bfloat16 h1 = __float2bfloat16(x1);
    __nv_bfloat16 l0 = __float2bfloat16(x0 - __bfloat162float(h0));
    __nv_bfloat16 l1 = __float2bfloat16(x1 - __bfloat162float(h1));
    __nv_bfloat162 hp = __halves2bfloat162(h0, h1);
    __nv_bfloat162 lp = __halves2bfloat162(l0, l1);
    h = *reinterpret_cast<uint32_t*>(&hp);
    l = *reinterpret_cast<uint32_t*>(&lp);
}
__device__ __forceinline__ uint32_t pack_h2(float a, float b) {
    __half2 h = __floats2half2_rn(a, b);
    return *reinterpret_cast<uint32_t*>(&h);
}

// ---------------- elementwise fp32 -> fp16 convert --------------------------------
__global__ __launch_bounds__(256)
void cvt_arr(const float4* __restrict__ src, uint2* __restrict__ dst, int n4)
{
    int i = blockIdx.x * blockDim.x + threadIdx.x;
    if (i >= n4) return;
    float4 v = src[i];
    dst[i] = make_uint2(pack_h2(v.x, v.y), pack_h2(v.z, v.w));
}

// ============================================================================
// FP16 single-pass projection GEMM: C = A * B^T. CTA 256x128, k64, 2-stage
// double-buffered cp.async (R10-proven loop structure). 256 thr, 8 warps 4x2,
// warp tile 64x64. smem/stage: A 32K | B 16K = 48KB; 2 stages = 96KB.
// outSplit: 0 -> C fp32 ; 1 -> Ch/Cl bf16 split.
// ============================================================================
__global__ __launch_bounds__(256)
void gemm_f16(const __half* __restrict__ Ag, const __half* __restrict__ Bg,
              float* __restrict__ C,
              __nv_bfloat16* __restrict__ Ch, __nv_bfloat16* __restrict__ Cl,
              int K, int lda, int ldb, int ldc, int outSplit)
{
    int rowBase = blockIdx.y * 256;
    int colBase = blockIdx.x * 128;

    extern __shared__ __align__(16) char sraw[];
    uint32_t sb = smem_u32(sraw);

    int tid = threadIdx.x, lane = tid & 31, w = tid >> 5;
    int wm = w >> 1, wn = w & 1;
    int lr = lane & 7, grp = lane >> 3;

    int agk = grp >> 1;
    uint32_t arow[4], arx[4];
    #pragma unroll
    for (int s = 0; s < 4; s++) {
        int r = wm * 64 + s * 16 + ((grp & 1) << 3) + lr;
        arow[s] = (uint32_t)r << 7;
        arx[s]  = r & 7;
    }
    int bgk = grp & 1;
    uint32_t brow[4], brx[4];
    #pragma unroll
    for (int p = 0; p < 4; p++) {
        int r = wn * 64 + p * 16 + ((grp >> 1) << 3) + lr;
        brow[p] = (uint32_t)r << 7;
        brx[p]  = r & 7;
    }

    float acc[4][8][4];
    #pragma unroll
    for (int s = 0; s < 4; s++)
        #pragma unroll
        for (int n = 0; n < 8; n++)
            #pragma unroll
            for (int j = 0; j < 4; j++) acc[s][n][j] = 0.f;

    int T = K >> 6;

    auto issue = [&](int t, int stg) {
        uint32_t base = sb + (uint32_t)stg * 49152u;
        int k0 = t << 6;
        #pragma unroll
        for (int i = 0; i < 8; i++) {           // A: 256 rows x 8 chunks
            int id = tid + (i << 8);
            int r = id >> 3, c = id & 7;
            uint32_t dst = base + ((uint32_t)r << 7) + (uint32_t)((c ^ (r & 7)) << 4);
            cpa16(dst, Ag + (size_t)(rowBase + r) * lda + k0 + (c << 3));
        }
        #pragma unroll
        for (int i = 0; i < 4; i++) {           // B: 128 rows x 8 chunks
            int id = tid + (i << 8);
            int r = id >> 3, c = id & 7;
            uint32_t dst = base + 32768u + ((uint32_t)r << 7) + (uint32_t)((c ^ (r & 7)) << 4);
            cpa16(dst, Bg + (size_t)(colBase + r) * ldb + k0 + (c << 3));
        }
        cpa_commit();
    };

    issue(0, 0);
    for (int t = 0; t < T; t++) {
        int stg = t & 1;
        if (t + 1 < T) { issue(t + 1, stg ^ 1); cpa_wait<1>(); }
        else          { cpa_wait<0>(); }
        __syncthreads();

        uint32_t aH = sb + (uint32_t)stg * 49152u;
        uint32_t bH = aH + 32768u;

        #pragma unroll
        for (int st = 0; st < 4; st++) {
            uint32_t Ah[4][4], Bh[8][2];
            #pragma unroll
            for (int s = 0; s < 4; s++) {
                uint32_t off = arow[s] + ((((st << 1) + agk) ^ arx[s]) << 4);
                ldsm4(Ah[s], aH + off);
            }
            #pragma unroll
            for (int p = 0; p < 4; p++) {
                uint32_t off = brow[p] + ((((st << 1) + bgk) ^ brx[p]) << 4);
                uint32_t tr[4];
                ldsm4(tr, bH + off);
                Bh[2*p][0] = tr[0]; Bh[2*p][1] = tr[1];
                Bh[2*p+1][0] = tr[2]; Bh[2*p+1][1] = tr[3];
            }
            #pragma unroll
            for (int s = 0; s < 4; s++)
                #pragma unroll
                for (int n = 0; n < 8; n++)
                    mma_fp16(acc[s][n], Ah[s], Bh[n]);
        }
        __syncthreads();
    }

    #pragma unroll
    for (int s = 0; s < 4; s++) {
        int r0 = rowBase + wm * 64 + s * 16 + (lane >> 2);
        #pragma unroll
        for (int n = 0; n < 8; n++) {
            int c0 = colBase + wn * 64 + n * 8 + ((lane & 3) << 1);
            if (!outSplit) {
                *(float2*)&C[(size_t)r0 * ldc + c0]       = make_float2(acc[s][n][0], acc[s][n][1]);
                *(float2*)&C[(size_t)(r0 + 8) * ldc + c0] = make_float2(acc[s][n][2], acc[s][n][3]);
            } else {
                uint32_t h0, l0, h1, l1;
                split2(acc[s][n][0], acc[s][n][1], h0, l0);
                split2(acc[s][n][2], acc[s][n][3], h1, l1);
                *(uint32_t*)&Ch[(size_t)r0 * ldc + c0]       = h0;
                *(uint32_t*)&Cl[(size_t)r0 * ldc + c0]       = l0;
                *(uint32_t*)&Ch[(size_t)(r0 + 8) * ldc + c0] = h1;
                *(uint32_t*)&Cl[(size_t)(r0 + 8) * ldc + c0] = l1;
            }
        }
    }
}

// ============================================================================
// FLASH ATTENTION (R10 proven): fused QK^T -> online softmax -> P*V,
// bf16-split 3-product. Output: single fp16 AO.
// ============================================================================
__global__ __launch_bounds__(256)
void flash_attn()
{
    int z = blockIdx.z;
    int b = z >> 4, h = z & 15;
    int qt = 15 - blockIdx.y;                 // heavy tiles first
    size_t qoff = ((size_t)(b * S_) + qt * 128) * D_ + h * HD_;
    size_t kvoff = (size_t)(b * S_) * D_ + h * HD_;
    const __nv_bfloat16* __restrict__ Qgh = g_Qh + qoff;
    const __nv_bfloat16* __restrict__ Qgl = g_Ql + qoff;
    const __nv_bfloat16* __restrict__ Kgh = g_Kh + kvoff;
    const __nv_bfloat16* __restrict__ Kgl = g_Kl + kvoff;
    const __nv_bfloat16* __restrict__ Vgh = g_Vh + kvoff;
    const __nv_bfloat16* __restrict__ Vgl = g_Vl + kvoff;
    __half* __restrict__ AOf = g_AOf + qoff;

    extern __shared__ __align__(16) char sraw[];
    uint32_t sb  = smem_u32(sraw);
    uint32_t sQh = sb, sQl = sb + 32768u;

    int tid = threadIdx.x, lane = tid & 31, w = tid >> 5;
    int lr = lane & 7, grp = lane >> 3;

    #pragma unroll
    for (int i = 0; i < 8; i++) {
        int id = tid + (i << 8);
        int r = id >> 4, c = id & 15;
        uint32_t dst = sQh + ((uint32_t)r << 8) + (uint32_t)((c ^ (r & 7)) << 4);
        cpa16(dst,           Qgh + (size_t)r * D_ + (c << 3));
        cpa16(dst + 32768u,  Qgl + (size_t)r * D_ + (c << 3));
    }

    auto issueKV = [&](int kt, int stg) {
        uint32_t base = sb + 65536u + (uint32_t)stg * 65536u;
        #pragma unroll
        for (int i = 0; i < 4; i++) {
            int id = tid + (i << 8);
            int r = id >> 4, c = id & 15;
            uint32_t dst = base + ((uint32_t)r << 8) + (uint32_t)((c ^ (r & 7)) << 4);
            cpa16(dst,          Kgh + (size_t)(kt * 64 + r) * D_ + (c << 3));
            cpa16(dst + 16384u, Kgl + (size_t)(kt * 64 + r) * D_ + (c << 3));
            cpa16(dst + 32768u, Vgh + (size_t)(kt * 64 + r) * D_ + (c << 3));
            cpa16(dst + 49152u, Vgl + (size_t)(kt * 64 + r) * D_ + (c << 3));
        }
    };

    issueKV(0, 0);
    cpa_commit();

    int qr = 16 * w + ((grp & 1) << 3) + lr;
    uint32_t aoffBase = ((uint32_t)qr << 8);
    uint32_t aXor = qr & 7;

    uint32_t Ah[8][4];
    float accO[16][4];
    #pragma unroll
    for (int n = 0; n < 16; n++)
        #pragma unroll
        for (int j = 0; j < 4; j++) accO[n][j] = 0.f;
    float m0 = -1e30f, m1 = -1e30f, l0 = 0.f, l1 = 0.f;

    int row0 = qt * 128 + 16 * w + (lane >> 2);

    int T = 2 * qt + 2;
    for (int kt = 0; kt < T; kt++) {
        int stg = kt & 1;
        if (kt + 1 < T) { issueKV(kt + 1, stg ^ 1); cpa_commit(); cpa_wait<1>(); }
        else            { cpa_wait<0>(); }
        __syncthreads();

        if (kt == 0) {
            #pragma unroll
            for (int st = 0; st < 8; st++) {
                uint32_t off = aoffBase + ((((st << 1) + (grp >> 1)) ^ aXor) << 4);
                ldsm4(Ah[st], sQh + off);
            }
        }

        uint32_t base = sb + 65536u + (uint32_t)stg * 65536u;
        uint32_t sKh = base, sKl = base + 16384u, sVh = base + 32768u, sVl = base + 49152u;

        float accs[8][4];
        #pragma unroll
        for (int n = 0; n < 8; n++)
            #pragma unroll
            for (int j = 0; j < 4; j++) accs[n][j] = 0.f;

        #pragma unroll
        for (int st = 0; st < 8; st++) {
            uint32_t aL[4];
            {
                uint32_t off = aoffBase + ((((st << 1) + (grp >> 1)) ^ aXor) << 4);
                ldsm4(aL, sQl + off);
            }
            #pragma unroll
            for (int p = 0; p < 4; p++) {
                int rr = p * 16 + ((grp >> 1) << 3) + lr;
                uint32_t off = ((uint32_t)rr << 8) + ((((st << 1) + (grp & 1)) ^ (rr & 7)) << 4);
                uint32_t th[4], tl[4];
                ldsm4(th, sKh + off);
                ldsm4(tl, sKl + off);
                uint32_t f0[2] = {th[0], th[1]}, f1[2] = {th[2], th[3]};
                uint32_t g0[2] = {tl[0], tl[1]}, g1[2] = {tl[2], tl[3]};
                mma_bf16(accs[2*p],   Ah[st], f0);
                mma_bf16(accs[2*p],   Ah[st], g0);
                mma_bf16(accs[2*p],   aL,     f0);
                mma_bf16(accs[2*p+1], Ah[st], f1);
                mma_bf16(accs[2*p+1], Ah[st], g1);
                mma_bf16(accs[2*p+1], aL,     f1);
            }
        }

        if (kt >= 2 * qt) {
            int colb = kt * 64 + ((lane & 3) << 1);
            #pragma unroll
            for (int n = 0; n < 8; n++) {
                int c0 = colb + n * 8;
                if (c0     > row0)     accs[n][0] = -1e30f;
                if (c0 + 1 > row0)     accs[n][1] = -1e30f;
                if (c0     > row0 + 8) accs[n][2] = -1e30f;
                if (c0 + 1 > row0 + 8) accs[n][3] = -1e30f;
            }
        }

        float mx0 = -1e30f, mx1 = -1e30f;
        #pragma unroll
        for (int n = 0; n < 8; n++) {
            mx0 = fmaxf(mx0, fmaxf(accs[n][0], accs[n][1]));
            mx1 = fmaxf(mx1, fmaxf(accs[n][2], accs[n][3]));
        }
        mx0 = fmaxf(mx0, __shfl_xor_sync(0xffffffffu, mx0, 1));
        mx0 = fmaxf(mx0, __shfl_xor_sync(0xffffffffu, mx0, 2));
        mx1 = fmaxf(mx1, __shfl_xor_sync(0xffffffffu, mx1, 1));
        mx1 = fmaxf(mx1, __shfl_xor_sync(0xffffffffu, mx1, 2));
        float nm0 = fmaxf(m0, mx0), nm1 = fmaxf(m1, mx1);
        float sf0 = __expf(m0 - nm0), sf1 = __expf(m1 - nm1);
        m0 = nm0; m1 = nm1;

        float rs0 = 0.f, rs1 = 0.f;
        #pragma unroll
        for (int n = 0; n < 8; n++) {
            accs[n][0] = __expf(accs[n][0] - nm0); rs0 += accs[n][0];
            accs[n][1] = __expf(accs[n][1] - nm0); rs0 += accs[n][1];
            accs[n][2] = __expf(accs[n][2] - nm1); rs1 += accs[n][2];
            accs[n][3] = __expf(accs[n][3] - nm1); rs1 += accs[n][3];
        }
        rs0 += __shfl_xor_sync(0xffffffffu, rs0, 1);
        rs0 += __shfl_xor_sync(0xffffffffu, rs0, 2);
        rs1 += __shfl_xor_sync(0xffffffffu, rs1, 1);
        rs1 += __shfl_xor_sync(0xffffffffu, rs1, 2);
        l0 = l0 * sf0 + rs0;
        l1 = l1 * sf1 + rs1;

        #pragma unroll
        for (int n = 0; n < 16; n++) {
            accO[n][0] *= sf0; accO[n][1] *= sf0;
            accO[n][2] *= sf1; accO[n][3] *= sf1;
        }

        #pragma unroll
        for (int kp = 0; kp < 4; kp++) {
            uint32_t ph[4], pl[4];
            split2(accs[2*kp][0],   accs[2*kp][1],   ph[0], pl[0]);
            split2(accs[2*kp][2],   accs[2*kp][3],   ph[1], pl[1]);
            split2(accs[2*kp+1][0], accs[2*kp+1][1], ph[2], pl[2]);
            split2(accs[2*kp+1][2], accs[2*kp+1][3], ph[3], pl[3]);

            int krb = ((grp & 1) << 3) + lr;
            #pragma unroll
            for (int j = 0; j < 8; j++) {
                int nc = j * 2 + (grp >> 1);
                uint32_t off = ((uint32_t)kp << 12) + ((uint32_t)krb << 8)
                             + (uint32_t)((nc ^ (krb & 7)) << 4);
                uint32_t th[4], tl[4];
                ldsm4t(th, sVh + off);
                ldsm4t(tl, sVl + off);
                uint32_t f0[2] = {th[0], th[1]}, f1[2] = {th[2], th[3]};
                uint32_t g0[2] = {tl[0], tl[1]}, g1[2] = {tl[2], tl[3]};
                mma_bf16(accO[2*j],   ph, f0);
                mma_bf16(accO[2*j],   ph, g0);
                mma_bf16(accO[2*j],   pl, f0);
                mma_bf16(accO[2*j+1], ph, f1);
                mma_bf16(accO[2*j+1], ph, g1);
                mma_bf16(accO[2*j+1], pl, f1);
            }
        }
        __syncthreads();
    }

    float inv0 = 1.f / l0, inv1 = 1.f / l1;
    int lrow = 16 * w + (lane >> 2);
    #pragma unroll
    for (int n = 0; n < 16; n++) {
        int c0 = n * 8 + ((lane & 3) << 1);
        *(uint32_t*)&AOf[(size_t)lrow * D_ + c0]       = pack_h2(accO[n][0] * inv0, accO[n][1] * inv0);
        *(uint32_t*)&AOf[(size_t)(lrow + 8) * D_ + c0] = pack_h2(accO[n][2] * inv1, accO[n][3] * inv1);
    }
}

// ---------------- RoPE tables -----------------------------------------------------
__global__ void rope_tables()
{
    int i = blockIdx.x * blockDim.x + threadIdx.x;
    if (i >= S_ * 64) return;
    int d = i & 63;
    int s = i >> 6;
    double inv = exp2(-(double)d / 64.0 * 13.287712379549449);   // log2(10000)
    double ang = (double)s * inv;
    g_cos[i] = (float)cos(ang);
    g_sin[i] = (float)sin(ang);
}

// ---------------- RoPE apply: fp32 Q/K -> split bf16 (scale folded into Q) -------
__global__ void rope_apply()
{
    size_t i = (size_t)blockIdx.x * blockDim.x + threadIdx.x;
    if (i >= (size_t)M_ * H_ * 64) return;
    int d = (int)(i & 63);
    int h = (int)((i >> 6) & (H_ - 1));
    int m = (int)(i >> 10);
    int s = m & (S_ - 1);
    float c  = g_cos[s * 64 + d];
    float sn = g_sin[s * 64 + d];
    const float scale = 0.08838834764831845f;   // 1/sqrt(128)
    size_t base = (size_t)m * D_ + h * HD_ + d;

    float q1 = g_Q[base], q2 = g_Q[base + 64];
    float qr1 = (q1 * c - q2 * sn) * scale;
    float qr2 = (q2 * c + q1 * sn) * scale;
    __nv_bfloat16 qh1 = __float2bfloat16(qr1);
    __nv_bfloat16 qh2 = __float2bfloat16(qr2);
    g_Qh[base]      = qh1; g_Ql[base]      = __float2bfloat16(qr1 - __bfloat162float(qh1));
    g_Qh[base + 64] = qh2; g_Ql[base + 64] = __float2bfloat16(qr2 - __bfloat162float(qh2));

    float k1 = g_K[base], k2 = g_K[base + 64];
    float kr1 = k1 * c - k2 * sn;
    float kr2 = k2 * c + k1 * sn;
    __nv_bfloat16 kh1 = __float2bfloat16(kr1);
    __nv_bfloat16 kh2 = __float2bfloat16(kr2);
    g_Kh[base]      = kh1; g_Kl[base]      = __float2bfloat16(kr1 - __bfloat162float(kh1));
    g_Kh[base + 64] = kh2; g_Kl[base + 64] = __float2bfloat16(kr2 - __bfloat162float(kh2));
}

// ---------------- launch ----------------------------------------------------------
extern "C" void kernel_launch(void* const* d_in, const int* in_sizes, int n_in,
                              void* d_out, int out_size)
{
    const float* x  = (const float*)d_in[0];
    const float* Wq = (const float*)d_in[1];
    const float* Wk = (const float*)d_in[2];
    const float* Wv = (const float*)d_in[3];
    const float* Wo = (const float*)d_in[4];
    float* out = (float*)d_out;

    float *Qp, *Kp;
    cudaGetSymbolAddress((void**)&Qp, g_Q);
    cudaGetSymbolAddress((void**)&Kp, g_K);
    __half *xf, *Wqf, *Wkf, *Wvf, *Wof, *AOf;
    __nv_bfloat16 *Vh, *Vl;
    cudaGetSymbolAddress((void**)&xf,  g_xf);
    cudaGetSymbolAddress((void**)&Wqf, g_Wqf);
    cudaGetSymbolAddress((void**)&Wkf, g_Wkf);
    cudaGetSymbolAddress((void**)&Wvf, g_Wvf);
    cudaGetSymbolAddress((void**)&Wof, g_Wof);
    cudaGetSymbolAddress((void**)&AOf, g_AOf);
    cudaGetSymbolAddress((void**)&Vh,  g_Vh);
    cudaGetSymbolAddress((void**)&Vl,  g_Vl);

    cudaFuncSetAttribute(gemm_f16,   cudaFuncAttributeMaxDynamicSharedMemorySize, 98304);
    cudaFuncSetAttribute(flash_attn, cudaFuncAttributeMaxDynamicSharedMemorySize, 196608);

    dim3 blk256(256);

    // 0) convert inputs to fp16
    {
        int n4x = (int)((size_t)M_ * D_ / 4);
        int n4w = (int)((size_t)D_ * D_ / 4);
        cvt_arr<<<(n4x + 255) / 256, blk256>>>((const float4*)x,  (uint2*)xf,  n4x);
        cvt_arr<<<(n4w + 255) / 256, blk256>>>((const float4*)Wq, (uint2*)Wqf, n4w);
        cvt_arr<<<(n4w + 255) / 256, blk256>>>((const float4*)Wk, (uint2*)Wkf, n4w);
        cvt_arr<<<(n4w + 255) / 256, blk256>>>((const float4*)Wv, (uint2*)Wvf, n4w);
        cvt_arr<<<(n4w + 255) / 256, blk256>>>((const float4*)Wo, (uint2*)Wof, n4w);
    }

    // 1) projections (fp16 single-pass): Q,K fp32 out (rope follows) ; V split bf16
    dim3 gProj(D_ / 128, M_ / 256, 1);
    gemm_f16<<<gProj, blk256, 98304>>>(xf, Wqf, Qp, 0, 0, D_, D_, D_, D_, 0);
    gemm_f16<<<gProj, blk256, 98304>>>(xf, Wkf, Kp, 0, 0, D_, D_, D_, D_, 0);
    gemm_f16<<<gProj, blk256, 98304>>>(xf, Wvf, 0, Vh, Vl, D_, D_, D_, D_, 1);

    // 2) RoPE
    rope_tables<<<(S_ * 64 + 255) / 256, blk256>>>();
    rope_apply<<<((size_t)M_ * H_ * 64 + 255) / 256, blk256>>>();

    // 3) fused attention (bf16-split): QK^T + online softmax + P*V -> fp16 AO
    dim3 gF(1, S_ / 128, B_ * H_);
    flash_attn<<<gF, blk256, 196608>>>();

    // 4) out = AO * Wo^T (fp16 single-pass), fp32 out
    gemm_f16<<<gProj, blk256, 98304>>>(AOf, Wof, out, 0, 0, D_, D_, D_, D_, 0);
}

// round 15
// speedup vs baseline: 3.3072x; 1.2690x over previous
#include <cuda_runtime.h>
#include <cuda_bf16.h>
#include <cuda_fp16.h>
#include <math.h>
#include <stdint.h>

#define B_  2
#define S_  2048
#define D_  2048
#define H_  16
#define HD_ 128
#define M_  (B_*S_)      // 4096 rows total

// ---------------- scratch (device globals; no allocation allowed) ----------------
__device__ float g_Q[(size_t)M_*D_];                 // fp32 proj out (pre-rope)
__device__ float g_K[(size_t)M_*D_];
__device__ float g_cos[S_*64];
__device__ float g_sin[S_*64];

__device__ __half g_xf[(size_t)M_*D_];
__device__ __half g_Wqf[(size_t)D_*D_];
__device__ __half g_Wkf[(size_t)D_*D_];
__device__ __half g_Wvf[(size_t)D_*D_];
__device__ __half g_Wof[(size_t)D_*D_];
__device__ __half g_Qf[(size_t)M_*D_];
__device__ __half g_Kf[(size_t)M_*D_];
__device__ __half g_Vf[(size_t)M_*D_];
__device__ __half g_AOf[(size_t)M_*D_];

// ---------------- helpers ---------------------------------------------------------
__device__ __forceinline__ uint32_t smem_u32(const void* p) {
    return (uint32_t)__cvta_generic_to_shared(p);
}
__device__ __forceinline__ void cpa16(uint32_t dst, const void* src) {
    asm volatile("cp.async.cg.shared.global [%0],[%1],16;" :: "r"(dst), "l"(src));
}
__device__ __forceinline__ void cpa_commit() { asm volatile("cp.async.commit_group;"); }
template<int N> __device__ __forceinline__ void cpa_wait() {
    asm volatile("cp.async.wait_group %0;" :: "n"(N));
}
__device__ __forceinline__ void ldsm4(uint32_t r[4], uint32_t addr) {
    asm volatile("ldmatrix.sync.aligned.m8n8.x4.shared.b16 {%0,%1,%2,%3},[%4];"
                 : "=r"(r[0]), "=r"(r[1]), "=r"(r[2]), "=r"(r[3]) : "r"(addr));
}
__device__ __forceinline__ void ldsm4t(uint32_t r[4], uint32_t addr) {
    asm volatile("ldmatrix.sync.aligned.m8n8.x4.trans.shared.b16 {%0,%1,%2,%3},[%4];"
                 : "=r"(r[0]), "=r"(r[1]), "=r"(r[2]), "=r"(r[3]) : "r"(addr));
}
__device__ __forceinline__ void mma_fp16(float d[4], const uint32_t a[4], const uint32_t b[2]) {
    asm volatile(
        "mma.sync.aligned.m16n8k16.row.col.f32.f16.f16.f32 "
        "{%0,%1,%2,%3},{%4,%5,%6,%7},{%8,%9},{%0,%1,%2,%3};"
        : "+f"(d[0]), "+f"(d[1]), "+f"(d[2]), "+f"(d[3])
        : "r"(a[0]), "r"(a[1]), "r"(a[2]), "r"(a[3]), "r"(b[0]), "r"(b[1]));
}
__device__ __forceinline__ uint32_t pack_h2(float a, float b) {
    __half2 h = __floats2half2_rn(a, b);
    return *reinterpret_cast<uint32_t*>(&h);
}

// ---------------- elementwise fp32 -> fp16 convert --------------------------------
__global__ __launch_bounds__(256)
void cvt_arr(const float4* __restrict__ src, uint2* __restrict__ dst, int n4)
{
    int i = blockIdx.x * blockDim.x + threadIdx.x;
    if (i >= n4) return;
    float4 v = src[i];
    dst[i] = make_uint2(pack_h2(v.x, v.y), pack_h2(v.z, v.w));
}

// ============================================================================
// FP16 single-pass GEMM: C = A * B^T. CTA 256x128, k64, 2-stage double-buffer
// (R10-proven loop). 256 thr, 8 warps 4x2, warp tile 64x64. smem 96KB.
// Output: C fp32 if Cf==0, else fp16 Cf.
// ============================================================================
__global__ __launch_bounds__(256)
void gemm_f16(const __half* __restrict__ Ag, const __half* __restrict__ Bg,
              float* __restrict__ C, __half* __restrict__ Cf,
              int K, int lda, int ldb, int ldc)
{
    int rowBase = blockIdx.y * 256;
    int colBase = blockIdx.x * 128;

    extern __shared__ __align__(16) char sraw[];
    uint32_t sb = smem_u32(sraw);

    int tid = threadIdx.x, lane = tid & 31, w = tid >> 5;
    int wm = w >> 1, wn = w & 1;
    int lr = lane & 7, grp = lane >> 3;

    int agk = grp >> 1;
    uint32_t arow[4], arx[4];
    #pragma unroll
    for (int s = 0; s < 4; s++) {
        int r = wm * 64 + s * 16 + ((grp & 1) << 3) + lr;
        arow[s] = (uint32_t)r << 7;
        arx[s]  = r & 7;
    }
    int bgk = grp & 1;
    uint32_t brow[4], brx[4];
    #pragma unroll
    for (int p = 0; p < 4; p++) {
        int r = wn * 64 + p * 16 + ((grp >> 1) << 3) + lr;
        brow[p] = (uint32_t)r << 7;
        brx[p]  = r & 7;
    }

    float acc[4][8][4];
    #pragma unroll
    for (int s = 0; s < 4; s++)
        #pragma unroll
        for (int n = 0; n < 8; n++)
            #pragma unroll
            for (int j = 0; j < 4; j++) acc[s][n][j] = 0.f;

    int T = K >> 6;

    auto issue = [&](int t, int stg) {
        uint32_t base = sb + (uint32_t)stg * 49152u;
        int k0 = t << 6;
        #pragma unroll
        for (int i = 0; i < 8; i++) {           // A: 256 rows x 8 chunks
            int id = tid + (i << 8);
            int r = id >> 3, c = id & 7;
            uint32_t dst = base + ((uint32_t)r << 7) + (uint32_t)((c ^ (r & 7)) << 4);
            cpa16(dst, Ag + (size_t)(rowBase + r) * lda + k0 + (c << 3));
        }
        #pragma unroll
        for (int i = 0; i < 4; i++) {           // B: 128 rows x 8 chunks
            int id = tid + (i << 8);
            int r = id >> 3, c = id & 7;
            uint32_t dst = base + 32768u + ((uint32_t)r << 7) + (uint32_t)((c ^ (r & 7)) << 4);
            cpa16(dst, Bg + (size_t)(colBase + r) * ldb + k0 + (c << 3));
        }
        cpa_commit();
    };

    issue(0, 0);
    for (int t = 0; t < T; t++) {
        int stg = t & 1;
        if (t + 1 < T) { issue(t + 1, stg ^ 1); cpa_wait<1>(); }
        else          { cpa_wait<0>(); }
        __syncthreads();

        uint32_t aH = sb + (uint32_t)stg * 49152u;
        uint32_t bH = aH + 32768u;

        #pragma unroll
        for (int st = 0; st < 4; st++) {
            uint32_t Ah[4][4], Bh[8][2];
            #pragma unroll
            for (int s = 0; s < 4; s++) {
                uint32_t off = arow[s] + ((((st << 1) + agk) ^ arx[s]) << 4);
                ldsm4(Ah[s], aH + off);
            }
            #pragma unroll
            for (int p = 0; p < 4; p++) {
                uint32_t off = brow[p] + ((((st << 1) + bgk) ^ brx[p]) << 4);
                uint32_t tr[4];
                ldsm4(tr, bH + off);
                Bh[2*p][0] = tr[0]; Bh[2*p][1] = tr[1];
                Bh[2*p+1][0] = tr[2]; Bh[2*p+1][1] = tr[3];
            }
            #pragma unroll
            for (int s = 0; s < 4; s++)
                #pragma unroll
                for (int n = 0; n < 8; n++)
                    mma_fp16(acc[s][n], Ah[s], Bh[n]);
        }
        __syncthreads();
    }

    #pragma unroll
    for (int s = 0; s < 4; s++) {
        int r0 = rowBase + wm * 64 + s * 16 + (lane >> 2);
        #pragma unroll
        for (int n = 0; n < 8; n++) {
            int c0 = colBase + wn * 64 + n * 8 + ((lane & 3) << 1);
            if (!Cf) {
                *(float2*)&C[(size_t)r0 * ldc + c0]       = make_float2(acc[s][n][0], acc[s][n][1]);
                *(float2*)&C[(size_t)(r0 + 8) * ldc + c0] = make_float2(acc[s][n][2], acc[s][n][3]);
            } else {
                *(uint32_t*)&Cf[(size_t)r0 * ldc + c0]       = pack_h2(acc[s][n][0], acc[s][n][1]);
                *(uint32_t*)&Cf[(size_t)(r0 + 8) * ldc + c0] = pack_h2(acc[s][n][2], acc[s][n][3]);
            }
        }
    }
}

// ============================================================================
// FLASH ATTENTION, full fp16 single-pass (Q, K, V, P fp16; fp32 accum).
// CTA: one (b,h) and 128 q rows. 8 warps, each owns 16 q rows x full width.
// smem: Qf 32K | 2 stages x { Kf 16K | Vf 16K } = 96K.
// Q pre-scaled by 1/sqrt(hd) in rope_apply. Output: fp16 AO.
// ============================================================================
__global__ __launch_bounds__(256)
void flash_attn()
{
    int z = blockIdx.z;
    int b = z >> 4, h = z & 15;
    int qt = 15 - blockIdx.y;                 // heavy tiles first
    size_t qoff = ((size_t)(b * S_) + qt * 128) * D_ + h * HD_;
    size_t kvoff = (size_t)(b * S_) * D_ + h * HD_;
    const __half* __restrict__ Qg = g_Qf + qoff;
    const __half* __restrict__ Kg = g_Kf + kvoff;
    const __half* __restrict__ Vg = g_Vf + kvoff;
    __half* __restrict__ AOf = g_AOf + qoff;

    extern __shared__ __align__(16) char sraw[];
    uint32_t sb = smem_u32(sraw);
    uint32_t sQ = sb;                          // 128 x 256B = 32K

    int tid = threadIdx.x, lane = tid & 31, w = tid >> 5;
    int lr = lane & 7, grp = lane >> 3;

    // ---- load Q tile (128 rows x 16 chunks) ----
    #pragma unroll
    for (int i = 0; i < 8; i++) {
        int id = tid + (i << 8);
        int r = id >> 4, c = id & 15;
        uint32_t dst = sQ + ((uint32_t)r << 8) + (uint32_t)((c ^ (r & 7)) << 4);
        cpa16(dst, Qg + (size_t)r * D_ + (c << 3));
    }

    auto issueKV = [&](int kt, int stg) {
        uint32_t base = sb + 32768u + (uint32_t)stg * 32768u;
        #pragma unroll
        for (int i = 0; i < 4; i++) {
            int id = tid + (i << 8);
            int r = id >> 4, c = id & 15;
            uint32_t dst = base + ((uint32_t)r << 8) + (uint32_t)((c ^ (r & 7)) << 4);
            cpa16(dst,           Kg + (size_t)(kt * 64 + r) * D_ + (c << 3));
            cpa16(dst + 16384u,  Vg + (size_t)(kt * 64 + r) * D_ + (c << 3));
        }
    };

    issueKV(0, 0);
    cpa_commit();

    int qr = 16 * w + ((grp & 1) << 3) + lr;
    uint32_t aoffBase = ((uint32_t)qr << 8);
    uint32_t aXor = qr & 7;

    uint32_t Ah[8][4];                          // Q frags, hoisted after first wait
    float accO[16][4];
    #pragma unroll
    for (int n = 0; n < 16; n++)
        #pragma unroll
        for (int j = 0; j < 4; j++) accO[n][j] = 0.f;
    float m0 = -1e30f, m1 = -1e30f, l0 = 0.f, l1 = 0.f;

    int row0 = qt * 128 + 16 * w + (lane >> 2);

    int T = 2 * qt + 2;
    for (int kt = 0; kt < T; kt++) {
        int stg = kt & 1;
        if (kt + 1 < T) { issueKV(kt + 1, stg ^ 1); cpa_commit(); cpa_wait<1>(); }
        else            { cpa_wait<0>(); }
        __syncthreads();

        if (kt == 0) {
            #pragma unroll
            for (int st = 0; st < 8; st++) {
                uint32_t off = aoffBase + ((((st << 1) + (grp >> 1)) ^ aXor) << 4);
                ldsm4(Ah[st], sQ + off);
            }
        }

        uint32_t base = sb + 32768u + (uint32_t)stg * 32768u;
        uint32_t sK = base, sV = base + 16384u;

        // ---- scores S = Q K^T (128 x 64), fp16 single-pass ----
        float accs[8][4];
        #pragma unroll
        for (int n = 0; n < 8; n++)
            #pragma unroll
            for (int j = 0; j < 4; j++) accs[n][j] = 0.f;

        #pragma unroll
        for (int st = 0; st < 8; st++) {
            #pragma unroll
            for (int p = 0; p < 4; p++) {
                int rr = p * 16 + ((grp >> 1) << 3) + lr;
                uint32_t off = ((uint32_t)rr << 8) + ((((st << 1) + (grp & 1)) ^ (rr & 7)) << 4);
                uint32_t th[4];
                ldsm4(th, sK + off);
                uint32_t f0[2] = {th[0], th[1]}, f1[2] = {th[2], th[3]};
                mma_fp16(accs[2*p],   Ah[st], f0);
                mma_fp16(accs[2*p+1], Ah[st], f1);
            }
        }

        // ---- causal mask (diagonal-crossing tiles only) ----
        if (kt >= 2 * qt) {
            int colb = kt * 64 + ((lane & 3) << 1);
            #pragma unroll
            for (int n = 0; n < 8; n++) {
                int c0 = colb + n * 8;
                if (c0     > row0)     accs[n][0] = -1e30f;
                if (c0 + 1 > row0)     accs[n][1] = -1e30f;
                if (c0     > row0 + 8) accs[n][2] = -1e30f;
                if (c0 + 1 > row0 + 8) accs[n][3] = -1e30f;
            }
        }

        // ---- online softmax update ----
        float mx0 = -1e30f, mx1 = -1e30f;
        #pragma unroll
        for (int n = 0; n < 8; n++) {
            mx0 = fmaxf(mx0, fmaxf(accs[n][0], accs[n][1]));
            mx1 = fmaxf(mx1, fmaxf(accs[n][2], accs[n][3]));
        }
        mx0 = fmaxf(mx0, __shfl_xor_sync(0xffffffffu, mx0, 1));
        mx0 = fmaxf(mx0, __shfl_xor_sync(0xffffffffu, mx0, 2));
        mx1 = fmaxf(mx1, __shfl_xor_sync(0xffffffffu, mx1, 1));
        mx1 = fmaxf(mx1, __shfl_xor_sync(0xffffffffu, mx1, 2));
        float nm0 = fmaxf(m0, mx0), nm1 = fmaxf(m1, mx1);
        float sf0 = __expf(m0 - nm0), sf1 = __expf(m1 - nm1);
        m0 = nm0; m1 = nm1;

        float rs0 = 0.f, rs1 = 0.f;
        #pragma unroll
        for (int n = 0; n < 8; n++) {
            accs[n][0] = __expf(accs[n][0] - nm0); rs0 += accs[n][0];
            accs[n][1] = __expf(accs[n][1] - nm0); rs0 += accs[n][1];
            accs[n][2] = __expf(accs[n][2] - nm1); rs1 += accs[n][2];
            accs[n][3] = __expf(accs[n][3] - nm1); rs1 += accs[n][3];
        }
        rs0 += __shfl_xor_sync(0xffffffffu, rs0, 1);
        rs0 += __shfl_xor_sync(0xffffffffu, rs0, 2);
        rs1 += __shfl_xor_sync(0xffffffffu, rs1, 1);
        rs1 += __shfl_xor_sync(0xffffffffu, rs1, 2);
        l0 = l0 * sf0 + rs0;
        l1 = l1 * sf1 + rs1;

        #pragma unroll
        for (int n = 0; n < 16; n++) {
            accO[n][0] *= sf0; accO[n][1] *= sf0;
            accO[n][2] *= sf1; accO[n][3] *= sf1;
        }

        // ---- O += P V, fp16 single-pass; P packed from accs layout ----
        #pragma unroll
        for (int kp = 0; kp < 4; kp++) {
            uint32_t ph[4];
            ph[0] = pack_h2(accs[2*kp][0],   accs[2*kp][1]);
            ph[1] = pack_h2(accs[2*kp][2],   accs[2*kp][3]);
            ph[2] = pack_h2(accs[2*kp+1][0], accs[2*kp+1][1]);
            ph[3] = pack_h2(accs[2*kp+1][2], accs[2*kp+1][3]);

            int krb = ((grp & 1) << 3) + lr;
            #pragma unroll
            for (int j = 0; j < 8; j++) {
                int nc = j * 2 + (grp >> 1);
                uint32_t off = ((uint32_t)kp << 12) + ((uint32_t)krb << 8)
                             + (uint32_t)((nc ^ (krb & 7)) << 4);
                uint32_t th[4];
                ldsm4t(th, sV + off);
                uint32_t f0[2] = {th[0], th[1]}, f1[2] = {th[2], th[3]};
                mma_fp16(accO[2*j],   ph, f0);
                mma_fp16(accO[2*j+1], ph, f1);
            }
        }
        __syncthreads();
    }

    // ---- finalize: O /= l, write fp16 ----
    float inv0 = 1.f / l0, inv1 = 1.f / l1;
    int lrow = 16 * w + (lane >> 2);
    #pragma unroll
    for (int n = 0; n < 16; n++) {
        int c0 = n * 8 + ((lane & 3) << 1);
        *(uint32_t*)&AOf[(size_t)lrow * D_ + c0]       = pack_h2(accO[n][0] * inv0, accO[n][1] * inv0);
        *(uint32_t*)&AOf[(size_t)(lrow + 8) * D_ + c0] = pack_h2(accO[n][2] * inv1, accO[n][3] * inv1);
    }
}

// ---------------- RoPE tables -----------------------------------------------------
__global__ void rope_tables()
{
    int i = blockIdx.x * blockDim.x + threadIdx.x;
    if (i >= S_ * 64) return;
    int d = i & 63;
    int s = i >> 6;
    double inv = exp2(-(double)d / 64.0 * 13.287712379549449);   // log2(10000)
    double ang = (double)s * inv;
    g_cos[i] = (float)cos(ang);
    g_sin[i] = (float)sin(ang);
}

// ---------------- RoPE apply: fp32 Q/K -> fp16 (scale folded into Q) --------------
__global__ void rope_apply()
{
    size_t i = (size_t)blockIdx.x * blockDim.x + threadIdx.x;
    if (i >= (size_t)M_ * H_ * 64) return;
    int d = (int)(i & 63);
    int h = (int)((i >> 6) & (H_ - 1));
    int m = (int)(i >> 10);
    int s = m & (S_ - 1);
    float c  = g_cos[s * 64 + d];
    float sn = g_sin[s * 64 + d];
    const float scale = 0.08838834764831845f;   // 1/sqrt(128)
    size_t base = (size_t)m * D_ + h * HD_ + d;

    float q1 = g_Q[base], q2 = g_Q[base + 64];
    g_Qf[base]      = __float2half((q1 * c - q2 * sn) * scale);
    g_Qf[base + 64] = __float2half((q2 * c + q1 * sn) * scale);

    float k1 = g_K[base], k2 = g_K[base + 64];
    g_Kf[base]      = __float2half(k1 * c - k2 * sn);
    g_Kf[base + 64] = __float2half(k2 * c + k1 * sn);
}

// ---------------- launch ----------------------------------------------------------
extern "C" void kernel_launch(void* const* d_in, const int* in_sizes, int n_in,
                              void* d_out, int out_size)
{
    const float* x  = (const float*)d_in[0];
    const float* Wq = (const float*)d_in[1];
    const float* Wk = (const float*)d_in[2];
    const float* Wv = (const float*)d_in[3];
    const float* Wo = (const float*)d_in[4];
    float* out = (float*)d_out;

    float *Qp, *Kp;
    cudaGetSymbolAddress((void**)&Qp, g_Q);
    cudaGetSymbolAddress((void**)&Kp, g_K);
    __half *xf, *Wqf, *Wkf, *Wvf, *Wof, *Vf, *AOf;
    cudaGetSymbolAddress((void**)&xf,  g_xf);
    cudaGetSymbolAddress((void**)&Wqf, g_Wqf);
    cudaGetSymbolAddress((void**)&Wkf, g_Wkf);
    cudaGetSymbolAddress((void**)&Wvf, g_Wvf);
    cudaGetSymbolAddress((void**)&Wof, g_Wof);
    cudaGetSymbolAddress((void**)&Vf,  g_Vf);
    cudaGetSymbolAddress((void**)&AOf, g_AOf);

    cudaFuncSetAttribute(gemm_f16,   cudaFuncAttributeMaxDynamicSharedMemorySize, 98304);
    cudaFuncSetAttribute(flash_attn, cudaFuncAttributeMaxDynamicSharedMemorySize, 98304);

    dim3 blk256(256);

    // 0) convert inputs to fp16
    {
        int n4x = (int)((size_t)M_ * D_ / 4);
        int n4w = (int)((size_t)D_ * D_ / 4);
        cvt_arr<<<(n4x + 255) / 256, blk256>>>((const float4*)x,  (uint2*)xf,  n4x);
        cvt_arr<<<(n4w + 255) / 256, blk256>>>((const float4*)Wq, (uint2*)Wqf, n4w);
        cvt_arr<<<(n4w + 255) / 256, blk256>>>((const float4*)Wk, (uint2*)Wkf, n4w);
        cvt_arr<<<(n4w + 255) / 256, blk256>>>((const float4*)Wv, (uint2*)Wvf, n4w);
        cvt_arr<<<(n4w + 255) / 256, blk256>>>((const float4*)Wo, (uint2*)Wof, n4w);
    }

    // 1) projections (fp16): Q,K fp32 out (rope follows) ; V fp16 out direct
    dim3 gProj(D_ / 128, M_ / 256, 1);
    gemm_f16<<<gProj, blk256, 98304>>>(xf, Wqf, Qp, 0, D_, D_, D_, D_);
    gemm_f16<<<gProj, blk256, 98304>>>(xf, Wkf, Kp, 0, D_, D_, D_, D_);
    gemm_f16<<<gProj, blk256, 98304>>>(xf, Wvf, 0, Vf, D_, D_, D_, D_);

    // 2) RoPE -> fp16 Q/K (scale folded into Q)
    rope_tables<<<(S_ * 64 + 255) / 256, blk256>>>();
    rope_apply<<<((size_t)M_ * H_ * 64 + 255) / 256, blk256>>>();

    // 3) fused attention (full fp16): QK^T + online softmax + P*V -> fp16 AO
    dim3 gF(1, S_ / 128, B_ * H_);
    flash_attn<<<gF, blk256, 98304>>>();

    // 4) out = AO * Wo^T (fp16), fp32 out
    gemm_f16<<<gProj, blk256, 98304>>>(AOf, Wof, out, 0, D_, D_, D_, D_);
}

// round 16
// speedup vs baseline: 3.6738x; 1.1108x over previous
#include <cuda_runtime.h>
#include <cuda_bf16.h>
#include <cuda_fp16.h>
#include <math.h>
#include <stdint.h>

#define B_  2
#define S_  2048
#define D_  2048
#define H_  16
#define HD_ 128
#define M_  (B_*S_)      // 4096 rows total

// ---------------- scratch (device globals; no allocation allowed) ----------------
__device__ float g_Q[(size_t)M_*D_];                 // fp32 proj out (pre-rope)
__device__ float g_K[(size_t)M_*D_];
__device__ float g_cos[S_*64];
__device__ float g_sin[S_*64];

__device__ __half g_xf[(size_t)M_*D_];
__device__ __half g_Wqf[(size_t)D_*D_];
__device__ __half g_Wkf[(size_t)D_*D_];
__device__ __half g_Wvf[(size_t)D_*D_];
__device__ __half g_Wof[(size_t)D_*D_];
__device__ __half g_Qf[(size_t)M_*D_];
__device__ __half g_Kf[(size_t)M_*D_];
__device__ __half g_Vf[(size_t)M_*D_];
__device__ __half g_AOf[(size_t)M_*D_];

// ---------------- helpers ---------------------------------------------------------
__device__ __forceinline__ uint32_t smem_u32(const void* p) {
    return (uint32_t)__cvta_generic_to_shared(p);
}
__device__ __forceinline__ void cpa16(uint32_t dst, const void* src) {
    asm volatile("cp.async.cg.shared.global [%0],[%1],16;" :: "r"(dst), "l"(src));
}
__device__ __forceinline__ void cpa_commit() { asm volatile("cp.async.commit_group;"); }
template<int N> __device__ __forceinline__ void cpa_wait() {
    asm volatile("cp.async.wait_group %0;" :: "n"(N));
}
__device__ __forceinline__ void ldsm4(uint32_t r[4], uint32_t addr) {
    asm volatile("ldmatrix.sync.aligned.m8n8.x4.shared.b16 {%0,%1,%2,%3},[%4];"
                 : "=r"(r[0]), "=r"(r[1]), "=r"(r[2]), "=r"(r[3]) : "r"(addr));
}
__device__ __forceinline__ void ldsm4t(uint32_t r[4], uint32_t addr) {
    asm volatile("ldmatrix.sync.aligned.m8n8.x4.trans.shared.b16 {%0,%1,%2,%3},[%4];"
                 : "=r"(r[0]), "=r"(r[1]), "=r"(r[2]), "=r"(r[3]) : "r"(addr));
}
__device__ __forceinline__ void mma_fp16(float d[4], const uint32_t a[4], const uint32_t b[2]) {
    asm volatile(
        "mma.sync.aligned.m16n8k16.row.col.f32.f16.f16.f32 "
        "{%0,%1,%2,%3},{%4,%5,%6,%7},{%8,%9},{%0,%1,%2,%3};"
        : "+f"(d[0]), "+f"(d[1]), "+f"(d[2]), "+f"(d[3])
        : "r"(a[0]), "r"(a[1]), "r"(a[2]), "r"(a[3]), "r"(b[0]), "r"(b[1]));
}
__device__ __forceinline__ uint32_t pack_h2(float a, float b) {
    __half2 h = __floats2half2_rn(a, b);
    return *reinterpret_cast<uint32_t*>(&h);
}

// ---------------- elementwise fp32 -> fp16 convert --------------------------------
__global__ __launch_bounds__(256)
void cvt_arr(const float4* __restrict__ src, uint2* __restrict__ dst, int n4)
{
    int i = blockIdx.x * blockDim.x + threadIdx.x;
    if (i >= n4) return;
    float4 v = src[i];
    dst[i] = make_uint2(pack_h2(v.x, v.y), pack_h2(v.z, v.w));
}

// ============================================================================
// FP16 GEMM, 2 CTAs/SM: C = A * B^T. CTA 128x128, k64, 2-stage double-buffer.
// 256 thr, 8 warps (4m x 2n), warp tile 32x64. smem 64KB/CTA.
// blockIdx.z selects operand/output set (QKV fusion); fp32 or fp16 output.
// ============================================================================
__global__ __launch_bounds__(256, 2)
void gemm128(const __half* __restrict__ Ag,
             const __half* __restrict__ B0, const __half* __restrict__ B1,
             const __half* __restrict__ B2,
             float* __restrict__ C0, float* __restrict__ C1,
             __half* __restrict__ C2,
             int K, int lda, int ldb, int ldc)
{
    const __half* Bg;
    float* Cf32 = 0;
    __half* Cf16 = 0;
    if (blockIdx.z == 0)      { Bg = B0; Cf32 = C0; }
    else if (blockIdx.z == 1) { Bg = B1; Cf32 = C1; }
    else                      { Bg = B2; Cf16 = C2; }

    int rowBase = blockIdx.y * 128;
    int colBase = blockIdx.x * 128;

    extern __shared__ __align__(16) char sraw[];
    uint32_t sb = smem_u32(sraw);

    int tid = threadIdx.x, lane = tid & 31, w = tid >> 5;
    int wm = w >> 1, wn = w & 1;
    int lr = lane & 7, grp = lane >> 3;

    int agk = grp >> 1;
    uint32_t arow[2], arx[2];
    #pragma unroll
    for (int s = 0; s < 2; s++) {
        int r = wm * 32 + s * 16 + ((grp & 1) << 3) + lr;
        arow[s] = (uint32_t)r << 7;
        arx[s]  = r & 7;
    }
    int bgk = grp & 1;
    uint32_t brow[4], brx[4];
    #pragma unroll
    for (int p = 0; p < 4; p++) {
        int r = wn * 64 + p * 16 + ((grp >> 1) << 3) + lr;
        brow[p] = (uint32_t)r << 7;
        brx[p]  = r & 7;
    }

    float acc[2][8][4];
    #pragma unroll
    for (int s = 0; s < 2; s++)
        #pragma unroll
        for (int n = 0; n < 8; n++)
            #pragma unroll
            for (int j = 0; j < 4; j++) acc[s][n][j] = 0.f;

    int T = K >> 6;

    auto issue = [&](int t, int stg) {
        uint32_t base = sb + (uint32_t)stg * 32768u;
        int k0 = t << 6;
        #pragma unroll
        for (int i = 0; i < 4; i++) {           // A: 128 rows x 8 chunks
            int id = tid + (i << 8);
            int r = id >> 3, c = id & 7;
            uint32_t dst = base + ((uint32_t)r << 7) + (uint32_t)((c ^ (r & 7)) << 4);
            cpa16(dst, Ag + (size_t)(rowBase + r) * lda + k0 + (c << 3));
        }
        #pragma unroll
        for (int i = 0; i < 4; i++) {           // B: 128 rows x 8 chunks
            int id = tid + (i << 8);
            int r = id >> 3, c = id & 7;
            uint32_t dst = base + 16384u + ((uint32_t)r << 7) + (uint32_t)((c ^ (r & 7)) << 4);
            cpa16(dst, Bg + (size_t)(colBase + r) * ldb + k0 + (c << 3));
        }
        cpa_commit();
    };

    issue(0, 0);
    for (int t = 0; t < T; t++) {
        int stg = t & 1;
        if (t + 1 < T) { issue(t + 1, stg ^ 1); cpa_wait<1>(); }
        else          { cpa_wait<0>(); }
        __syncthreads();

        uint32_t aH = sb + (uint32_t)stg * 32768u;
        uint32_t bH = aH + 16384u;

        #pragma unroll
        for (int st = 0; st < 4; st++) {
            uint32_t Ah[2][4], Bh[8][2];
            #pragma unroll
            for (int s = 0; s < 2; s++) {
                uint32_t off = arow[s] + ((((st << 1) + agk) ^ arx[s]) << 4);
                ldsm4(Ah[s], aH + off);
            }
            #pragma unroll
            for (int p = 0; p < 4; p++) {
                uint32_t off = brow[p] + ((((st << 1) + bgk) ^ brx[p]) << 4);
                uint32_t tr[4];
                ldsm4(tr, bH + off);
                Bh[2*p][0] = tr[0]; Bh[2*p][1] = tr[1];
                Bh[2*p+1][0] = tr[2]; Bh[2*p+1][1] = tr[3];
            }
            #pragma unroll
            for (int s = 0; s < 2; s++)
                #pragma unroll
                for (int n = 0; n < 8; n++)
                    mma_fp16(acc[s][n], Ah[s], Bh[n]);
        }
        __syncthreads();
    }

    #pragma unroll
    for (int s = 0; s < 2; s++) {
        int r0 = rowBase + wm * 32 + s * 16 + (lane >> 2);
        #pragma unroll
        for (int n = 0; n < 8; n++) {
            int c0 = colBase + wn * 64 + n * 8 + ((lane & 3) << 1);
            if (Cf16) {
                *(uint32_t*)&Cf16[(size_t)r0 * ldc + c0]       = pack_h2(acc[s][n][0], acc[s][n][1]);
                *(uint32_t*)&Cf16[(size_t)(r0 + 8) * ldc + c0] = pack_h2(acc[s][n][2], acc[s][n][3]);
            } else {
                *(float2*)&Cf32[(size_t)r0 * ldc + c0]       = make_float2(acc[s][n][0], acc[s][n][1]);
                *(float2*)&Cf32[(size_t)(r0 + 8) * ldc + c0] = make_float2(acc[s][n][2], acc[s][n][3]);
            }
        }
    }
}

// ============================================================================
// FLASH ATTENTION, full fp16 single-pass (R14 proven).
// smem: Qf 32K | 2 stages x { Kf 16K | Vf 16K } = 96K.
// ============================================================================
__global__ __launch_bounds__(256)
void flash_attn()
{
    int z = blockIdx.z;
    int b = z >> 4, h = z & 15;
    int qt = 15 - blockIdx.y;                 // heavy tiles first
    size_t qoff = ((size_t)(b * S_) + qt * 128) * D_ + h * HD_;
    size_t kvoff = (size_t)(b * S_) * D_ + h * HD_;
    const __half* __restrict__ Qg = g_Qf + qoff;
    const __half* __restrict__ Kg = g_Kf + kvoff;
    const __half* __restrict__ Vg = g_Vf + kvoff;
    __half* __restrict__ AOf = g_AOf + qoff;

    extern __shared__ __align__(16) char sraw[];
    uint32_t sb = smem_u32(sraw);
    uint32_t sQ = sb;

    int tid = threadIdx.x, lane = tid & 31, w = tid >> 5;
    int lr = lane & 7, grp = lane >> 3;

    #pragma unroll
    for (int i = 0; i < 8; i++) {
        int id = tid + (i << 8);
        int r = id >> 4, c = id & 15;
        uint32_t dst = sQ + ((uint32_t)r << 8) + (uint32_t)((c ^ (r & 7)) << 4);
        cpa16(dst, Qg + (size_t)r * D_ + (c << 3));
    }

    auto issueKV = [&](int kt, int stg) {
        uint32_t base = sb + 32768u + (uint32_t)stg * 32768u;
        #pragma unroll
        for (int i = 0; i < 4; i++) {
            int id = tid + (i << 8);
            int r = id >> 4, c = id & 15;
            uint32_t dst = base + ((uint32_t)r << 8) + (uint32_t)((c ^ (r & 7)) << 4);
            cpa16(dst,           Kg + (size_t)(kt * 64 + r) * D_ + (c << 3));
            cpa16(dst + 16384u,  Vg + (size_t)(kt * 64 + r) * D_ + (c << 3));
        }
    };

    issueKV(0, 0);
    cpa_commit();

    int qr = 16 * w + ((grp & 1) << 3) + lr;
    uint32_t aoffBase = ((uint32_t)qr << 8);
    uint32_t aXor = qr & 7;

    uint32_t Ah[8][4];
    float accO[16][4];
    #pragma unroll
    for (int n = 0; n < 16; n++)
        #pragma unroll
        for (int j = 0; j < 4; j++) accO[n][j] = 0.f;
    float m0 = -1e30f, m1 = -1e30f, l0 = 0.f, l1 = 0.f;

    int row0 = qt * 128 + 16 * w + (lane >> 2);

    int T = 2 * qt + 2;
    for (int kt = 0; kt < T; kt++) {
        int stg = kt & 1;
        if (kt + 1 < T) { issueKV(kt + 1, stg ^ 1); cpa_commit(); cpa_wait<1>(); }
        else            { cpa_wait<0>(); }
        __syncthreads();

        if (kt == 0) {
            #pragma unroll
            for (int st = 0; st < 8; st++) {
                uint32_t off = aoffBase + ((((st << 1) + (grp >> 1)) ^ aXor) << 4);
                ldsm4(Ah[st], sQ + off);
            }
        }

        uint32_t base = sb + 32768u + (uint32_t)stg * 32768u;
        uint32_t sK = base, sV = base + 16384u;

        float accs[8][4];
        #pragma unroll
        for (int n = 0; n < 8; n++)
            #pragma unroll
            for (int j = 0; j < 4; j++) accs[n][j] = 0.f;

        #pragma unroll
        for (int st = 0; st < 8; st++) {
            #pragma unroll
            for (int p = 0; p < 4; p++) {
                int rr = p * 16 + ((grp >> 1) << 3) + lr;
                uint32_t off = ((uint32_t)rr << 8) + ((((st << 1) + (grp & 1)) ^ (rr & 7)) << 4);
                uint32_t th[4];
                ldsm4(th, sK + off);
                uint32_t f0[2] = {th[0], th[1]}, f1[2] = {th[2], th[3]};
                mma_fp16(accs[2*p],   Ah[st], f0);
                mma_fp16(accs[2*p+1], Ah[st], f1);
            }
        }

        if (kt >= 2 * qt) {
            int colb = kt * 64 + ((lane & 3) << 1);
            #pragma unroll
            for (int n = 0; n < 8; n++) {
                int c0 = colb + n * 8;
                if (c0     > row0)     accs[n][0] = -1e30f;
                if (c0 + 1 > row0)     accs[n][1] = -1e30f;
                if (c0     > row0 + 8) accs[n][2] = -1e30f;
                if (c0 + 1 > row0 + 8) accs[n][3] = -1e30f;
            }
        }

        float mx0 = -1e30f, mx1 = -1e30f;
        #pragma unroll
        for (int n = 0; n < 8; n++) {
            mx0 = fmaxf(mx0, fmaxf(accs[n][0], accs[n][1]));
            mx1 = fmaxf(mx1, fmaxf(accs[n][2], accs[n][3]));
        }
        mx0 = fmaxf(mx0, __shfl_xor_sync(0xffffffffu, mx0, 1));
        mx0 = fmaxf(mx0, __shfl_xor_sync(0xffffffffu, mx0, 2));
        mx1 = fmaxf(mx1, __shfl_xor_sync(0xffffffffu, mx1, 1));
        mx1 = fmaxf(mx1, __shfl_xor_sync(0xffffffffu, mx1, 2));
        float nm0 = fmaxf(m0, mx0), nm1 = fmaxf(m1, mx1);
        float sf0 = __expf(m0 - nm0), sf1 = __expf(m1 - nm1);
        m0 = nm0; m1 = nm1;

        float rs0 = 0.f, rs1 = 0.f;
        #pragma unroll
        for (int n = 0; n < 8; n++) {
            accs[n][0] = __expf(accs[n][0] - nm0); rs0 += accs[n][0];
            accs[n][1] = __expf(accs[n][1] - nm0); rs0 += accs[n][1];
            accs[n][2] = __expf(accs[n][2] - nm1); rs1 += accs[n][2];
            accs[n][3] = __expf(accs[n][3] - nm1); rs1 += accs[n][3];
        }
        rs0 += __shfl_xor_sync(0xffffffffu, rs0, 1);
        rs0 += __shfl_xor_sync(0xffffffffu, rs0, 2);
        rs1 += __shfl_xor_sync(0xffffffffu, rs1, 1);
        rs1 += __shfl_xor_sync(0xffffffffu, rs1, 2);
        l0 = l0 * sf0 + rs0;
        l1 = l1 * sf1 + rs1;

        #pragma unroll
        for (int n = 0; n < 16; n++) {
            accO[n][0] *= sf0; accO[n][1] *= sf0;
            accO[n][2] *= sf1; accO[n][3] *= sf1;
        }

        #pragma unroll
        for (int kp = 0; kp < 4; kp++) {
            uint32_t ph[4];
            ph[0] = pack_h2(accs[2*kp][0],   accs[2*kp][1]);
            ph[1] = pack_h2(accs[2*kp][2],   accs[2*kp][3]);
            ph[2] = pack_h2(accs[2*kp+1][0], accs[2*kp+1][1]);
            ph[3] = pack_h2(accs[2*kp+1][2], accs[2*kp+1][3]);

            int krb = ((grp & 1) << 3) + lr;
            #pragma unroll
            for (int j = 0; j < 8; j++) {
                int nc = j * 2 + (grp >> 1);
                uint32_t off = ((uint32_t)kp << 12) + ((uint32_t)krb << 8)
                             + (uint32_t)((nc ^ (krb & 7)) << 4);
                uint32_t th[4];
                ldsm4t(th, sV + off);
                uint32_t f0[2] = {th[0], th[1]}, f1[2] = {th[2], th[3]};
                mma_fp16(accO[2*j],   ph, f0);
                mma_fp16(accO[2*j+1], ph, f1);
            }
        }
        __syncthreads();
    }

    float inv0 = 1.f / l0, inv1 = 1.f / l1;
    int lrow = 16 * w + (lane >> 2);
    #pragma unroll
    for (int n = 0; n < 16; n++) {
        int c0 = n * 8 + ((lane & 3) << 1);
        *(uint32_t*)&AOf[(size_t)lrow * D_ + c0]       = pack_h2(accO[n][0] * inv0, accO[n][1] * inv0);
        *(uint32_t*)&AOf[(size_t)(lrow + 8) * D_ + c0] = pack_h2(accO[n][2] * inv1, accO[n][3] * inv1);
    }
}

// ---------------- RoPE tables -----------------------------------------------------
__global__ void rope_tables()
{
    int i = blockIdx.x * blockDim.x + threadIdx.x;
    if (i >= S_ * 64) return;
    int d = i & 63;
    int s = i >> 6;
    double inv = exp2(-(double)d / 64.0 * 13.287712379549449);   // log2(10000)
    double ang = (double)s * inv;
    g_cos[i] = (float)cos(ang);
    g_sin[i] = (float)sin(ang);
}

// ---------------- RoPE apply: fp32 Q/K -> fp16 (scale folded into Q) --------------
__global__ void rope_apply()
{
    size_t i = (size_t)blockIdx.x * blockDim.x + threadIdx.x;
    if (i >= (size_t)M_ * H_ * 64) return;
    int d = (int)(i & 63);
    int h = (int)((i >> 6) & (H_ - 1));
    int m = (int)(i >> 10);
    int s = m & (S_ - 1);
    float c  = g_cos[s * 64 + d];
    float sn = g_sin[s * 64 + d];
    const float scale = 0.08838834764831845f;   // 1/sqrt(128)
    size_t base = (size_t)m * D_ + h * HD_ + d;

    float q1 = g_Q[base], q2 = g_Q[base + 64];
    g_Qf[base]      = __float2half((q1 * c - q2 * sn) * scale);
    g_Qf[base + 64] = __float2half((q2 * c + q1 * sn) * scale);

    float k1 = g_K[base], k2 = g_K[base + 64];
    g_Kf[base]      = __float2half(k1 * c - k2 * sn);
    g_Kf[base + 64] = __float2half(k2 * c + k1 * sn);
}

// ---------------- launch ----------------------------------------------------------
extern "C" void kernel_launch(void* const* d_in, const int* in_sizes, int n_in,
                              void* d_out, int out_size)
{
    const float* x  = (const float*)d_in[0];
    const float* Wq = (const float*)d_in[1];
    const float* Wk = (const float*)d_in[2];
    const float* Wv = (const float*)d_in[3];
    const float* Wo = (const float*)d_in[4];
    float* out = (float*)d_out;

    float *Qp, *Kp;
    cudaGetSymbolAddress((void**)&Qp, g_Q);
    cudaGetSymbolAddress((void**)&Kp, g_K);
    __half *xf, *Wqf, *Wkf, *Wvf, *Wof, *Vf, *AOf;
    cudaGetSymbolAddress((void**)&xf,  g_xf);
    cudaGetSymbolAddress((void**)&Wqf, g_Wqf);
    cudaGetSymbolAddress((void**)&Wkf, g_Wkf);
    cudaGetSymbolAddress((void**)&Wvf, g_Wvf);
    cudaGetSymbolAddress((void**)&Wof, g_Wof);
    cudaGetSymbolAddress((void**)&Vf,  g_Vf);
    cudaGetSymbolAddress((void**)&AOf, g_AOf);

    cudaFuncSetAttribute(gemm128,    cudaFuncAttributeMaxDynamicSharedMemorySize, 65536);
    cudaFuncSetAttribute(flash_attn, cudaFuncAttributeMaxDynamicSharedMemorySize, 98304);

    dim3 blk256(256);

    // 0) convert inputs to fp16
    {
        int n4x = (int)((size_t)M_ * D_ / 4);
        int n4w = (int)((size_t)D_ * D_ / 4);
        cvt_arr<<<(n4x + 255) / 256, blk256>>>((const float4*)x,  (uint2*)xf,  n4x);
        cvt_arr<<<(n4w + 255) / 256, blk256>>>((const float4*)Wq, (uint2*)Wqf, n4w);
        cvt_arr<<<(n4w + 255) / 256, blk256>>>((const float4*)Wk, (uint2*)Wkf, n4w);
        cvt_arr<<<(n4w + 255) / 256, blk256>>>((const float4*)Wv, (uint2*)Wvf, n4w);
        cvt_arr<<<(n4w + 255) / 256, blk256>>>((const float4*)Wo, (uint2*)Wof, n4w);
    }

    // 1) fused QKV projections: z=0 -> Q fp32, z=1 -> K fp32, z=2 -> V fp16
    dim3 gQKV(D_ / 128, M_ / 128, 3);
    gemm128<<<gQKV, blk256, 65536>>>(xf, Wqf, Wkf, Wvf, Qp, Kp, Vf,
                                     D_, D_, D_, D_);

    // 2) RoPE -> fp16 Q/K (scale folded into Q)
    rope_tables<<<(S_ * 64 + 255) / 256, blk256>>>();
    rope_apply<<<((size_t)M_ * H_ * 64 + 255) / 256, blk256>>>();

    // 3) fused attention (full fp16): QK^T + online softmax + P*V -> fp16 AO
    dim3 gF(1, S_ / 128, B_ * H_);
    flash_attn<<<gF, blk256, 98304>>>();

    // 4) out = AO * Wo^T, fp32 out
    dim3 gWo(D_ / 128, M_ / 128, 1);
    gemm128<<<gWo, blk256, 65536>>>(AOf, Wof, 0, 0, out, 0, 0,
                                    D_, D_, D_, D_);
}

// round 17
// speedup vs baseline: 3.9446x; 1.0737x over previous
#include <cuda_runtime.h>
#include <cuda_bf16.h>
#include <cuda_fp16.h>
#include <math.h>
#include <stdint.h>

#define B_  2
#define S_  2048
#define D_  2048
#define H_  16
#define HD_ 128
#define M_  (B_*S_)      // 4096 rows total

// ---------------- scratch (device globals; no allocation allowed) ----------------
__device__ float g_cos[S_*64];
__device__ float g_sin[S_*64];

__device__ __half g_xf[(size_t)M_*D_];
__device__ __half g_Wqf[(size_t)D_*D_];
__device__ __half g_Wkf[(size_t)D_*D_];
__device__ __half g_Wvf[(size_t)D_*D_];
__device__ __half g_Wof[(size_t)D_*D_];
__device__ __half g_Qpre[(size_t)M_*D_];
__device__ __half g_Kpre[(size_t)M_*D_];
__device__ __half g_Qf[(size_t)M_*D_];
__device__ __half g_Kf[(size_t)M_*D_];
__device__ __half g_Vf[(size_t)M_*D_];
__device__ __half g_AOf[(size_t)M_*D_];

// ---------------- helpers ---------------------------------------------------------
__device__ __forceinline__ uint32_t smem_u32(const void* p) {
    return (uint32_t)__cvta_generic_to_shared(p);
}
__device__ __forceinline__ void cpa16(uint32_t dst, const void* src) {
    asm volatile("cp.async.cg.shared.global [%0],[%1],16;" :: "r"(dst), "l"(src));
}
__device__ __forceinline__ void cpa_commit() { asm volatile("cp.async.commit_group;"); }
template<int N> __device__ __forceinline__ void cpa_wait() {
    asm volatile("cp.async.wait_group %0;" :: "n"(N));
}
__device__ __forceinline__ void ldsm4(uint32_t r[4], uint32_t addr) {
    asm volatile("ldmatrix.sync.aligned.m8n8.x4.shared.b16 {%0,%1,%2,%3},[%4];"
                 : "=r"(r[0]), "=r"(r[1]), "=r"(r[2]), "=r"(r[3]) : "r"(addr));
}
__device__ __forceinline__ void ldsm4t(uint32_t r[4], uint32_t addr) {
    asm volatile("ldmatrix.sync.aligned.m8n8.x4.trans.shared.b16 {%0,%1,%2,%3},[%4];"
                 : "=r"(r[0]), "=r"(r[1]), "=r"(r[2]), "=r"(r[3]) : "r"(addr));
}
__device__ __forceinline__ void mma_fp16(float d[4], const uint32_t a[4], const uint32_t b[2]) {
    asm volatile(
        "mma.sync.aligned.m16n8k16.row.col.f32.f16.f16.f32 "
        "{%0,%1,%2,%3},{%4,%5,%6,%7},{%8,%9},{%0,%1,%2,%3};"
        : "+f"(d[0]), "+f"(d[1]), "+f"(d[2]), "+f"(d[3])
        : "r"(a[0]), "r"(a[1]), "r"(a[2]), "r"(a[3]), "r"(b[0]), "r"(b[1]));
}
__device__ __forceinline__ uint32_t pack_h2(float a, float b) {
    __half2 h = __floats2half2_rn(a, b);
    return *reinterpret_cast<uint32_t*>(&h);
}

// ---------------- elementwise fp32 -> fp16 convert --------------------------------
__global__ __launch_bounds__(256)
void cvt_arr(const float4* __restrict__ src, uint2* __restrict__ dst, int n4)
{
    int i = blockIdx.x * blockDim.x + threadIdx.x;
    if (i >= n4) return;
    float4 v = src[i];
    dst[i] = make_uint2(pack_h2(v.x, v.y), pack_h2(v.z, v.w));
}

// ============================================================================
// FP16 GEMM, 2 CTAs/SM (R15 proven): C = A * B^T. CTA 128x128, k64, 2-stage.
// 256 thr, 8 warps (4m x 2n), warp tile 32x64. smem 64KB/CTA.
// z selects B/output; fp32 output if F0 != 0 (Wo), else fp16 per-z.
// ============================================================================
__global__ __launch_bounds__(256, 2)
void gemm128(const __half* __restrict__ Ag,
             const __half* __restrict__ B0, const __half* __restrict__ B1,
             const __half* __restrict__ B2,
             __half* __restrict__ H0, __half* __restrict__ H1,
             __half* __restrict__ H2,
             float* __restrict__ F0,
             int K, int lda, int ldb, int ldc)
{
    const __half* Bg;
    __half* Cf16 = 0;
    if (blockIdx.z == 0)      { Bg = B0; Cf16 = H0; }
    else if (blockIdx.z == 1) { Bg = B1; Cf16 = H1; }
    else                      { Bg = B2; Cf16 = H2; }

    int rowBase = blockIdx.y * 128;
    int colBase = blockIdx.x * 128;

    extern __shared__ __align__(16) char sraw[];
    uint32_t sb = smem_u32(sraw);

    int tid = threadIdx.x, lane = tid & 31, w = tid >> 5;
    int wm = w >> 1, wn = w & 1;
    int lr = lane & 7, grp = lane >> 3;

    int agk = grp >> 1;
    uint32_t arow[2], arx[2];
    #pragma unroll
    for (int s = 0; s < 2; s++) {
        int r = wm * 32 + s * 16 + ((grp & 1) << 3) + lr;
        arow[s] = (uint32_t)r << 7;
        arx[s]  = r & 7;
    }
    int bgk = grp & 1;
    uint32_t brow[4], brx[4];
    #pragma unroll
    for (int p = 0; p < 4; p++) {
        int r = wn * 64 + p * 16 + ((grp >> 1) << 3) + lr;
        brow[p] = (uint32_t)r << 7;
        brx[p]  = r & 7;
    }

    float acc[2][8][4];
    #pragma unroll
    for (int s = 0; s < 2; s++)
        #pragma unroll
        for (int n = 0; n < 8; n++)
            #pragma unroll
            for (int j = 0; j < 4; j++) acc[s][n][j] = 0.f;

    int T = K >> 6;

    auto issue = [&](int t, int stg) {
        uint32_t base = sb + (uint32_t)stg * 32768u;
        int k0 = t << 6;
        #pragma unroll
        for (int i = 0; i < 4; i++) {
            int id = tid + (i << 8);
            int r = id >> 3, c = id & 7;
            uint32_t dst = base + ((uint32_t)r << 7) + (uint32_t)((c ^ (r & 7)) << 4);
            cpa16(dst, Ag + (size_t)(rowBase + r) * lda + k0 + (c << 3));
        }
        #pragma unroll
        for (int i = 0; i < 4; i++) {
            int id = tid + (i << 8);
            int r = id >> 3, c = id & 7;
            uint32_t dst = base + 16384u + ((uint32_t)r << 7) + (uint32_t)((c ^ (r & 7)) << 4);
            cpa16(dst, Bg + (size_t)(colBase + r) * ldb + k0 + (c << 3));
        }
        cpa_commit();
    };

    issue(0, 0);
    for (int t = 0; t < T; t++) {
        int stg = t & 1;
        if (t + 1 < T) { issue(t + 1, stg ^ 1); cpa_wait<1>(); }
        else          { cpa_wait<0>(); }
        __syncthreads();

        uint32_t aH = sb + (uint32_t)stg * 32768u;
        uint32_t bH = aH + 16384u;

        #pragma unroll
        for (int st = 0; st < 4; st++) {
            uint32_t Ah[2][4], Bh[8][2];
            #pragma unroll
            for (int s = 0; s < 2; s++) {
                uint32_t off = arow[s] + ((((st << 1) + agk) ^ arx[s]) << 4);
                ldsm4(Ah[s], aH + off);
            }
            #pragma unroll
            for (int p = 0; p < 4; p++) {
                uint32_t off = brow[p] + ((((st << 1) + bgk) ^ brx[p]) << 4);
                uint32_t tr[4];
                ldsm4(tr, bH + off);
                Bh[2*p][0] = tr[0]; Bh[2*p][1] = tr[1];
                Bh[2*p+1][0] = tr[2]; Bh[2*p+1][1] = tr[3];
            }
            #pragma unroll
            for (int s = 0; s < 2; s++)
                #pragma unroll
                for (int n = 0; n < 8; n++)
                    mma_fp16(acc[s][n], Ah[s], Bh[n]);
        }
        __syncthreads();
    }

    #pragma unroll
    for (int s = 0; s < 2; s++) {
        int r0 = rowBase + wm * 32 + s * 16 + (lane >> 2);
        #pragma unroll
        for (int n = 0; n < 8; n++) {
            int c0 = colBase + wn * 64 + n * 8 + ((lane & 3) << 1);
            if (F0) {
                *(float2*)&F0[(size_t)r0 * ldc + c0]       = make_float2(acc[s][n][0], acc[s][n][1]);
                *(float2*)&F0[(size_t)(r0 + 8) * ldc + c0] = make_float2(acc[s][n][2], acc[s][n][3]);
            } else {
                *(uint32_t*)&Cf16[(size_t)r0 * ldc + c0]       = pack_h2(acc[s][n][0], acc[s][n][1]);
                *(uint32_t*)&Cf16[(size_t)(r0 + 8) * ldc + c0] = pack_h2(acc[s][n][2], acc[s][n][3]);
            }
        }
    }
}

// ============================================================================
// FLASH ATTENTION, full fp16, 2 CTAs/SM: q-tile 64 rows, 128 threads (4 warps
// x 16 rows), KV tiles of 64 tokens double-buffered.
// smem: Qf 16K | 2 stages x { Kf 16K | Vf 16K } = 80K/CTA.
// Q pre-scaled by 1/sqrt(hd) in rope_apply. Output: fp16 AO.
// ============================================================================
__global__ __launch_bounds__(128, 2)
void flash_attn()
{
    int z = blockIdx.z;
    int b = z >> 4, h = z & 15;
    int qt = 31 - blockIdx.y;                 // heavy tiles first; 64-row q tiles
    size_t qoff = ((size_t)(b * S_) + qt * 64) * D_ + h * HD_;
    size_t kvoff = (size_t)(b * S_) * D_ + h * HD_;
    const __half* __restrict__ Qg = g_Qf + qoff;
    const __half* __restrict__ Kg = g_Kf + kvoff;
    const __half* __restrict__ Vg = g_Vf + kvoff;
    __half* __restrict__ AOf = g_AOf + qoff;

    extern __shared__ __align__(16) char sraw[];
    uint32_t sb = smem_u32(sraw);
    uint32_t sQ = sb;                          // 64 x 256B = 16K

    int tid = threadIdx.x, lane = tid & 31, w = tid >> 5;   // w: 0..3
    int lr = lane & 7, grp = lane >> 3;

    // ---- load Q tile (64 rows x 16 chunks) ----
    #pragma unroll
    for (int i = 0; i < 8; i++) {
        int id = tid + (i << 7);
        int r = id >> 4, c = id & 15;
        uint32_t dst = sQ + ((uint32_t)r << 8) + (uint32_t)((c ^ (r & 7)) << 4);
        cpa16(dst, Qg + (size_t)r * D_ + (c << 3));
    }

    auto issueKV = [&](int kt, int stg) {
        uint32_t base = sb + 16384u + (uint32_t)stg * 32768u;
        #pragma unroll
        for (int i = 0; i < 8; i++) {
            int id = tid + (i << 7);
            int r = id >> 4, c = id & 15;
            uint32_t dst = base + ((uint32_t)r << 8) + (uint32_t)((c ^ (r & 7)) << 4);
            cpa16(dst,           Kg + (size_t)(kt * 64 + r) * D_ + (c << 3));
            cpa16(dst + 16384u,  Vg + (size_t)(kt * 64 + r) * D_ + (c << 3));
        }
    };

    issueKV(0, 0);
    cpa_commit();

    int qr = 16 * w + ((grp & 1) << 3) + lr;
    uint32_t aoffBase = ((uint32_t)qr << 8);
    uint32_t aXor = qr & 7;

    uint32_t Ah[8][4];
    float accO[16][4];
    #pragma unroll
    for (int n = 0; n < 16; n++)
        #pragma unroll
        for (int j = 0; j < 4; j++) accO[n][j] = 0.f;
    float m0 = -1e30f, m1 = -1e30f, l0 = 0.f, l1 = 0.f;

    int row0 = qt * 64 + 16 * w + (lane >> 2);

    int T = qt + 1;
    for (int kt = 0; kt < T; kt++) {
        int stg = kt & 1;
        if (kt + 1 < T) { issueKV(kt + 1, stg ^ 1); cpa_commit(); cpa_wait<1>(); }
        else            { cpa_wait<0>(); }
        __syncthreads();

        if (kt == 0) {
            #pragma unroll
            for (int st = 0; st < 8; st++) {
                uint32_t off = aoffBase + ((((st << 1) + (grp >> 1)) ^ aXor) << 4);
                ldsm4(Ah[st], sQ + off);
            }
        }

        uint32_t base = sb + 16384u + (uint32_t)stg * 32768u;
        uint32_t sK = base, sV = base + 16384u;

        // ---- scores S = Q K^T (64 x 64) ----
        float accs[8][4];
        #pragma unroll
        for (int n = 0; n < 8; n++)
            #pragma unroll
            for (int j = 0; j < 4; j++) accs[n][j] = 0.f;

        #pragma unroll
        for (int st = 0; st < 8; st++) {
            #pragma unroll
            for (int p = 0; p < 4; p++) {
                int rr = p * 16 + ((grp >> 1) << 3) + lr;
                uint32_t off = ((uint32_t)rr << 8) + ((((st << 1) + (grp & 1)) ^ (rr & 7)) << 4);
                uint32_t th[4];
                ldsm4(th, sK + off);
                uint32_t f0[2] = {th[0], th[1]}, f1[2] = {th[2], th[3]};
                mma_fp16(accs[2*p],   Ah[st], f0);
                mma_fp16(accs[2*p+1], Ah[st], f1);
            }
        }

        // ---- causal mask (last tile only) ----
        if (kt == qt) {
            int colb = kt * 64 + ((lane & 3) << 1);
            #pragma unroll
            for (int n = 0; n < 8; n++) {
                int c0 = colb + n * 8;
                if (c0     > row0)     accs[n][0] = -1e30f;
                if (c0 + 1 > row0)     accs[n][1] = -1e30f;
                if (c0     > row0 + 8) accs[n][2] = -1e30f;
                if (c0 + 1 > row0 + 8) accs[n][3] = -1e30f;
            }
        }

        // ---- online softmax update ----
        float mx0 = -1e30f, mx1 = -1e30f;
        #pragma unroll
        for (int n = 0; n < 8; n++) {
            mx0 = fmaxf(mx0, fmaxf(accs[n][0], accs[n][1]));
            mx1 = fmaxf(mx1, fmaxf(accs[n][2], accs[n][3]));
        }
        mx0 = fmaxf(mx0, __shfl_xor_sync(0xffffffffu, mx0, 1));
        mx0 = fmaxf(mx0, __shfl_xor_sync(0xffffffffu, mx0, 2));
        mx1 = fmaxf(mx1, __shfl_xor_sync(0xffffffffu, mx1, 1));
        mx1 = fmaxf(mx1, __shfl_xor_sync(0xffffffffu, mx1, 2));
        float nm0 = fmaxf(m0, mx0), nm1 = fmaxf(m1, mx1);
        float sf0 = __expf(m0 - nm0), sf1 = __expf(m1 - nm1);
        m0 = nm0; m1 = nm1;

        float rs0 = 0.f, rs1 = 0.f;
        #pragma unroll
        for (int n = 0; n < 8; n++) {
            accs[n][0] = __expf(accs[n][0] - nm0); rs0 += accs[n][0];
            accs[n][1] = __expf(accs[n][1] - nm0); rs0 += accs[n][1];
            accs[n][2] = __expf(accs[n][2] - nm1); rs1 += accs[n][2];
            accs[n][3] = __expf(accs[n][3] - nm1); rs1 += accs[n][3];
        }
        rs0 += __shfl_xor_sync(0xffffffffu, rs0, 1);
        rs0 += __shfl_xor_sync(0xffffffffu, rs0, 2);
        rs1 += __shfl_xor_sync(0xffffffffu, rs1, 1);
        rs1 += __shfl_xor_sync(0xffffffffu, rs1, 2);
        l0 = l0 * sf0 + rs0;
        l1 = l1 * sf1 + rs1;

        #pragma unroll
        for (int n = 0; n < 16; n++) {
            accO[n][0] *= sf0; accO[n][1] *= sf0;
            accO[n][2] *= sf1; accO[n][3] *= sf1;
        }

        // ---- O += P V ----
        #pragma unroll
        for (int kp = 0; kp < 4; kp++) {
            uint32_t ph[4];
            ph[0] = pack_h2(accs[2*kp][0],   accs[2*kp][1]);
            ph[1] = pack_h2(accs[2*kp][2],   accs[2*kp][3]);
            ph[2] = pack_h2(accs[2*kp+1][0], accs[2*kp+1][1]);
            ph[3] = pack_h2(accs[2*kp+1][2], accs[2*kp+1][3]);

            int krb = ((grp & 1) << 3) + lr;
            #pragma unroll
            for (int j = 0; j < 8; j++) {
                int nc = j * 2 + (grp >> 1);
                uint32_t off = ((uint32_t)kp << 12) + ((uint32_t)krb << 8)
                             + (uint32_t)((nc ^ (krb & 7)) << 4);
                uint32_t th[4];
                ldsm4t(th, sV + off);
                uint32_t f0[2] = {th[0], th[1]}, f1[2] = {th[2], th[3]};
                mma_fp16(accO[2*j],   ph, f0);
                mma_fp16(accO[2*j+1], ph, f1);
            }
        }
        __syncthreads();
    }

    float inv0 = 1.f / l0, inv1 = 1.f / l1;
    int lrow = 16 * w + (lane >> 2);
    #pragma unroll
    for (int n = 0; n < 16; n++) {
        int c0 = n * 8 + ((lane & 3) << 1);
        *(uint32_t*)&AOf[(size_t)lrow * D_ + c0]       = pack_h2(accO[n][0] * inv0, accO[n][1] * inv0);
        *(uint32_t*)&AOf[(size_t)(lrow + 8) * D_ + c0] = pack_h2(accO[n][2] * inv1, accO[n][3] * inv1);
    }
}

// ---------------- RoPE tables -----------------------------------------------------
__global__ void rope_tables()
{
    int i = blockIdx.x * blockDim.x + threadIdx.x;
    if (i >= S_ * 64) return;
    int d = i & 63;
    int s = i >> 6;
    double inv = exp2(-(double)d / 64.0 * 13.287712379549449);   // log2(10000)
    double ang = (double)s * inv;
    g_cos[i] = (float)cos(ang);
    g_sin[i] = (float)sin(ang);
}

// ---------------- RoPE apply: fp16 Q/K -> fp16 (scale folded into Q) --------------
__global__ void rope_apply()
{
    size_t i = (size_t)blockIdx.x * blockDim.x + threadIdx.x;
    if (i >= (size_t)M_ * H_ * 64) return;
    int d = (int)(i & 63);
    int h = (int)((i >> 6) & (H_ - 1));
    int m = (int)(i >> 10);
    int s = m & (S_ - 1);
    float c  = g_cos[s * 64 + d];
    float sn = g_sin[s * 64 + d];
    const float scale = 0.08838834764831845f;   // 1/sqrt(128)
    size_t base = (size_t)m * D_ + h * HD_ + d;

    float q1 = __half2float(g_Qpre[base]), q2 = __half2float(g_Qpre[base + 64]);
    g_Qf[base]      = __float2half((q1 * c - q2 * sn) * scale);
    g_Qf[base + 64] = __float2half((q2 * c + q1 * sn) * scale);

    float k1 = __half2float(g_Kpre[base]), k2 = __half2float(g_Kpre[base + 64]);
    g_Kf[base]      = __float2half(k1 * c - k2 * sn);
    g_Kf[base + 64] = __float2half(k2 * c + k1 * sn);
}

// ---------------- launch ----------------------------------------------------------
extern "C" void kernel_launch(void* const* d_in, const int* in_sizes, int n_in,
                              void* d_out, int out_size)
{
    const float* x  = (const float*)d_in[0];
    const float* Wq = (const float*)d_in[1];
    const float* Wk = (const float*)d_in[2];
    const float* Wv = (const float*)d_in[3];
    const float* Wo = (const float*)d_in[4];
    float* out = (float*)d_out;

    __half *xf, *Wqf, *Wkf, *Wvf, *Wof, *Qpre, *Kpre, *Vf, *AOf;
    cudaGetSymbolAddress((void**)&xf,   g_xf);
    cudaGetSymbolAddress((void**)&Wqf,  g_Wqf);
    cudaGetSymbolAddress((void**)&Wkf,  g_Wkf);
    cudaGetSymbolAddress((void**)&Wvf,  g_Wvf);
    cudaGetSymbolAddress((void**)&Wof,  g_Wof);
    cudaGetSymbolAddress((void**)&Qpre, g_Qpre);
    cudaGetSymbolAddress((void**)&Kpre, g_Kpre);
    cudaGetSymbolAddress((void**)&Vf,   g_Vf);
    cudaGetSymbolAddress((void**)&AOf,  g_AOf);

    cudaFuncSetAttribute(gemm128,    cudaFuncAttributeMaxDynamicSharedMemorySize, 65536);
    cudaFuncSetAttribute(flash_attn, cudaFuncAttributeMaxDynamicSharedMemorySize, 81920);

    dim3 blk256(256), blk128(128);

    // 0) convert inputs to fp16
    {
        int n4x = (int)((size_t)M_ * D_ / 4);
        int n4w = (int)((size_t)D_ * D_ / 4);
        cvt_arr<<<(n4x + 255) / 256, blk256>>>((const float4*)x,  (uint2*)xf,  n4x);
        cvt_arr<<<(n4w + 255) / 256, blk256>>>((const float4*)Wq, (uint2*)Wqf, n4w);
        cvt_arr<<<(n4w + 255) / 256, blk256>>>((const float4*)Wk, (uint2*)Wkf, n4w);
        cvt_arr<<<(n4w + 255) / 256, blk256>>>((const float4*)Wv, (uint2*)Wvf, n4w);
        cvt_arr<<<(n4w + 255) / 256, blk256>>>((const float4*)Wo, (uint2*)Wof, n4w);
    }

    // 1) fused QKV projections: z=0 -> Qpre, z=1 -> Kpre, z=2 -> V (all fp16)
    dim3 gQKV(D_ / 128, M_ / 128, 3);
    gemm128<<<gQKV, blk256, 65536>>>(xf, Wqf, Wkf, Wvf, Qpre, Kpre, Vf, 0,
                                     D_, D_, D_, D_);

    // 2) RoPE -> fp16 Q/K (scale folded into Q)
    rope_tables<<<(S_ * 64 + 255) / 256, blk256>>>();
    rope_apply<<<((size_t)M_ * H_ * 64 + 255) / 256, blk256>>>();

    // 3) fused attention (full fp16, 64-row q tiles, 2 CTAs/SM)
    dim3 gF(1, S_ / 64, B_ * H_);
    flash_attn<<<gF, blk128, 81920>>>();

    // 4) out = AO * Wo^T, fp32 out
    dim3 gWo(D_ / 128, M_ / 128, 1);
    gemm128<<<gWo, blk256, 65536>>>(AOf, Wof, 0, 0, 0, 0, 0, out,
                                    D_, D_, D_, D_);
}